// round 1
// baseline (speedup 1.0000x reference)
#include <cuda_runtime.h>
#include <math.h>
#include <float.h>

#define BATCH 2048
#define SEQ   32
#define DIM   1024
#define HID   1024
#define MS    4096
#define NK    32

// ---------------- scratch (device globals: no allocation allowed) ----------
__device__ float g_query[BATCH * HID];   // [B,H]
__device__ float g_sim  [BATCH * MS];    // raw sim = query @ mem^T  (UNscaled)
__device__ float g_actA [BATCH * MS];
__device__ float g_actB [BATCH * MS];
__device__ float g_gate [BATCH];
__device__ float g_vals [BATCH * NK];
__device__ int   g_idx  [BATCH * NK];
__device__ float g_read [BATCH * HID];
__device__ float g_orow [BATCH * DIM];

// ---------------------------------------------------------------------------
// Kernel 1: fused encoder GEMM + tanh + mean over S
// query[b,h] = (1/S) * sum_s tanh( sum_d x[b,s,d]*W[d,h] + bias[h] )
// grid: (H/128, B), block: 256
// ---------------------------------------------------------------------------
__global__ void k_encoder(const float* __restrict__ x,
                          const float* __restrict__ W,
                          const float* __restrict__ bias,
                          float* __restrict__ query)
{
    __shared__ float As[32][32];    // [k][s]
    __shared__ float Bs[32][128];   // [k][h]
    __shared__ float red[8][128];

    const int b  = blockIdx.y;
    const int h0 = blockIdx.x * 128;
    const int tid = threadIdx.x;

    const int sIdx = (tid >> 5) * 4;        // 0..28
    const int hIdx = (tid & 31) * 4;        // 0..124

    float acc[4][4];
#pragma unroll
    for (int i = 0; i < 4; i++)
#pragma unroll
        for (int j = 0; j < 4; j++) acc[i][j] = 0.f;

    const float* xb = x + (size_t)b * SEQ * DIM;

    for (int d0 = 0; d0 < DIM; d0 += 32) {
        // load A tile transposed: As[k][s] = x[b][s][d0+k]
        {
            int s  = tid >> 3;          // 0..31
            int kq = (tid & 7) * 4;     // 0..28
            float4 v = *(const float4*)(xb + s * DIM + d0 + kq);
            As[kq + 0][s] = v.x; As[kq + 1][s] = v.y;
            As[kq + 2][s] = v.z; As[kq + 3][s] = v.w;
        }
        // load B tile: Bs[k][h] = W[d0+k][h0+h]
        {
            int kr = tid >> 5;          // 0..7
            int hq = (tid & 31) * 4;
#pragma unroll
            for (int p = 0; p < 4; p++) {
                int row = kr + p * 8;
                *(float4*)&Bs[row][hq] = *(const float4*)(W + (size_t)(d0 + row) * HID + h0 + hq);
            }
        }
        __syncthreads();
#pragma unroll
        for (int k = 0; k < 32; k++) {
            float4 a = *(const float4*)&As[k][sIdx];
            float4 bv = *(const float4*)&Bs[k][hIdx];
            float av[4] = {a.x, a.y, a.z, a.w};
            float bw[4] = {bv.x, bv.y, bv.z, bv.w};
#pragma unroll
            for (int i = 0; i < 4; i++)
#pragma unroll
                for (int j = 0; j < 4; j++) acc[i][j] += av[i] * bw[j];
        }
        __syncthreads();
    }

    // tanh + partial mean over this thread's 4 s-rows
    float part[4];
#pragma unroll
    for (int j = 0; j < 4; j++) {
        float bh = bias[h0 + hIdx + j];
        float s = 0.f;
#pragma unroll
        for (int i = 0; i < 4; i++) s += tanhf(acc[i][j] + bh);
        part[j] = s;
    }
    int ty = tid >> 5;
    red[ty][hIdx + 0] = part[0]; red[ty][hIdx + 1] = part[1];
    red[ty][hIdx + 2] = part[2]; red[ty][hIdx + 3] = part[3];
    __syncthreads();
    if (tid < 128) {
        float s = 0.f;
#pragma unroll
        for (int g = 0; g < 8; g++) s += red[g][tid];
        query[(size_t)b * HID + h0 + tid] = s * (1.0f / SEQ);
    }
}

// ---------------------------------------------------------------------------
// Kernel 2: NT GEMM  C[r][c] = sum_k A[r][k] * B[c][k]
// (sim = query @ mem^T).  tiles 64x64, KT=32. grid: (N/64, M/64), block 256
// ---------------------------------------------------------------------------
__global__ void k_gemm_nt(const float* __restrict__ A,
                          const float* __restrict__ B,
                          float* __restrict__ C,
                          int N, int K)
{
    __shared__ float As[32][64];
    __shared__ float Bs[32][64];

    const int tid = threadIdx.x;
    const int r0 = blockIdx.y * 64;
    const int c0 = blockIdx.x * 64;
    const int r4 = (tid >> 4) * 4;   // 0..60
    const int c4 = (tid & 15) * 4;   // 0..60

    float acc[4][4];
#pragma unroll
    for (int i = 0; i < 4; i++)
#pragma unroll
        for (int j = 0; j < 4; j++) acc[i][j] = 0.f;

    for (int k0 = 0; k0 < K; k0 += 32) {
        int kq = (tid & 7) * 4;
#pragma unroll
        for (int p = 0; p < 2; p++) {
            int row = (tid >> 3) + p * 32;
            float4 va = *(const float4*)(A + (size_t)(r0 + row) * K + k0 + kq);
            As[kq + 0][row] = va.x; As[kq + 1][row] = va.y;
            As[kq + 2][row] = va.z; As[kq + 3][row] = va.w;
            float4 vb = *(const float4*)(B + (size_t)(c0 + row) * K + k0 + kq);
            Bs[kq + 0][row] = vb.x; Bs[kq + 1][row] = vb.y;
            Bs[kq + 2][row] = vb.z; Bs[kq + 3][row] = vb.w;
        }
        __syncthreads();
#pragma unroll
        for (int k = 0; k < 32; k++) {
            float4 a = *(const float4*)&As[k][r4];
            float4 b = *(const float4*)&Bs[k][c4];
            float av[4] = {a.x, a.y, a.z, a.w};
            float bv[4] = {b.x, b.y, b.z, b.w};
#pragma unroll
            for (int i = 0; i < 4; i++)
#pragma unroll
                for (int j = 0; j < 4; j++) acc[i][j] += av[i] * bv[j];
        }
        __syncthreads();
    }
#pragma unroll
    for (int i = 0; i < 4; i++) {
        float4 v = make_float4(acc[i][0], acc[i][1], acc[i][2], acc[i][3]);
        *(float4*)(C + (size_t)(r0 + r4 + i) * N + c0 + c4) = v;
    }
}

// ---------------------------------------------------------------------------
// Kernel 3: NN GEMM  C[r][c] = sum_k A[r][k] * B[k][c]  (+optional bias+tanh)
// tiles 64x64, KT=32. grid: (N/64, M/64), block 256
// ---------------------------------------------------------------------------
template <bool TANH>
__global__ void k_gemm_nn(const float* __restrict__ A,
                          const float* __restrict__ B,
                          float* __restrict__ C,
                          int N, int K,
                          const float* __restrict__ bias)
{
    __shared__ float As[32][64];
    __shared__ float Bs[32][64];

    const int tid = threadIdx.x;
    const int r0 = blockIdx.y * 64;
    const int c0 = blockIdx.x * 64;
    const int r4 = (tid >> 4) * 4;
    const int c4 = (tid & 15) * 4;

    float acc[4][4];
#pragma unroll
    for (int i = 0; i < 4; i++)
#pragma unroll
        for (int j = 0; j < 4; j++) acc[i][j] = 0.f;

    for (int k0 = 0; k0 < K; k0 += 32) {
        // A tile transposed
        {
            int kq = (tid & 7) * 4;
#pragma unroll
            for (int p = 0; p < 2; p++) {
                int row = (tid >> 3) + p * 32;
                float4 va = *(const float4*)(A + (size_t)(r0 + row) * K + k0 + kq);
                As[kq + 0][row] = va.x; As[kq + 1][row] = va.y;
                As[kq + 2][row] = va.z; As[kq + 3][row] = va.w;
            }
        }
        // B tile direct
        {
            int nq = (tid & 15) * 4;
#pragma unroll
            for (int p = 0; p < 2; p++) {
                int row = (tid >> 4) + p * 16;
                *(float4*)&Bs[row][nq] = *(const float4*)(B + (size_t)(k0 + row) * N + c0 + nq);
            }
        }
        __syncthreads();
#pragma unroll
        for (int k = 0; k < 32; k++) {
            float4 a = *(const float4*)&As[k][r4];
            float4 b = *(const float4*)&Bs[k][c4];
            float av[4] = {a.x, a.y, a.z, a.w};
            float bv[4] = {b.x, b.y, b.z, b.w};
#pragma unroll
            for (int i = 0; i < 4; i++)
#pragma unroll
                for (int j = 0; j < 4; j++) acc[i][j] += av[i] * bv[j];
        }
        __syncthreads();
    }
#pragma unroll
    for (int i = 0; i < 4; i++) {
        float4 v;
        if (TANH) {
            v = make_float4(tanhf(acc[i][0] + bias[c0 + c4 + 0]),
                            tanhf(acc[i][1] + bias[c0 + c4 + 1]),
                            tanhf(acc[i][2] + bias[c0 + c4 + 2]),
                            tanhf(acc[i][3] + bias[c0 + c4 + 3]));
        } else {
            v = make_float4(acc[i][0], acc[i][1], acc[i][2], acc[i][3]);
        }
        *(float4*)(C + (size_t)(r0 + r4 + i) * N + c0 + c4) = v;
    }
}

// ---------------------------------------------------------------------------
// Kernel 4: gate[b] = sigmoid(dot(query[b], w_curv) + b_curv)
// grid 2048, block 128
// ---------------------------------------------------------------------------
__global__ void k_gate(const float* __restrict__ query,
                       const float* __restrict__ w_curv,
                       const float* __restrict__ b_curv)
{
    __shared__ float red[4];
    int b = blockIdx.x, tid = threadIdx.x;
    float s = 0.f;
    for (int h = tid; h < HID; h += 128)
        s += query[(size_t)b * HID + h] * w_curv[h];
#pragma unroll
    for (int o = 16; o; o >>= 1) s += __shfl_xor_sync(0xffffffffu, s, o);
    if ((tid & 31) == 0) red[tid >> 5] = s;
    __syncthreads();
    if (tid == 0) {
        float t = red[0] + red[1] + red[2] + red[3] + b_curv[0];
        g_gate[b] = 1.0f / (1.0f + expf(-t));
    }
}

// ---------------------------------------------------------------------------
// Kernel 5: top-32 of scaled sim per row (iterative argmax, sorted desc)
// grid 2048, block 256
// ---------------------------------------------------------------------------
__global__ void k_topk(const float* __restrict__ sim,
                       const float* __restrict__ temperature)
{
    __shared__ float sv[MS];
    __shared__ float rv[256];
    __shared__ int   ri[256];

    int b = blockIdx.x, tid = threadIdx.x;
    float scale = (0.5f + g_gate[b]) / fmaxf(temperature[0], 1e-6f);
    const float* row = sim + (size_t)b * MS;
    for (int i = tid; i < MS; i += 256) sv[i] = row[i] * scale;
    __syncthreads();

    for (int k = 0; k < NK; k++) {
        float bv = -FLT_MAX; int bi = MS;
        for (int i = tid; i < MS; i += 256) {
            float v = sv[i];
            if (v > bv || (v == bv && i < bi)) { bv = v; bi = i; }
        }
        rv[tid] = bv; ri[tid] = bi;
        __syncthreads();
        for (int off = 128; off; off >>= 1) {
            if (tid < off) {
                float v2 = rv[tid + off]; int i2 = ri[tid + off];
                if (v2 > rv[tid] || (v2 == rv[tid] && i2 < ri[tid])) {
                    rv[tid] = v2; ri[tid] = i2;
                }
            }
            __syncthreads();
        }
        if (tid == 0) {
            g_vals[(size_t)b * NK + k] = rv[0];
            g_idx [(size_t)b * NK + k] = ri[0];
            sv[ri[0]] = -FLT_MAX;
        }
        __syncthreads();
    }
}

// ---------------------------------------------------------------------------
// Kernel 6: row softmax over M=4096.  grid 2048, block 256
// ---------------------------------------------------------------------------
__global__ void k_softmax(const float* __restrict__ in, float* __restrict__ out)
{
    __shared__ float sv[MS];
    __shared__ float red[256];
    int b = blockIdx.x, tid = threadIdx.x;
    const float* row = in + (size_t)b * MS;

    float mx = -FLT_MAX;
    for (int i = tid; i < MS; i += 256) { float v = row[i]; sv[i] = v; mx = fmaxf(mx, v); }
    red[tid] = mx; __syncthreads();
    for (int off = 128; off; off >>= 1) {
        if (tid < off) red[tid] = fmaxf(red[tid], red[tid + off]);
        __syncthreads();
    }
    mx = red[0]; __syncthreads();

    float s = 0.f;
    for (int i = tid; i < MS; i += 256) { float e = expf(sv[i] - mx); sv[i] = e; s += e; }
    red[tid] = s; __syncthreads();
    for (int off = 128; off; off >>= 1) {
        if (tid < off) red[tid] += red[tid + off];
        __syncthreads();
    }
    float inv = 1.0f / red[0];
    float* orow = out + (size_t)b * MS;
    for (int i = tid; i < MS; i += 256) orow[i] = sv[i] * inv;
}

// ---------------------------------------------------------------------------
// Kernel 7: combine softmax(vals + act[idx]) and read = comb @ mem[idx]
// grid 2048, block 256
// ---------------------------------------------------------------------------
__global__ void k_combine(const float* __restrict__ act,
                          const float* __restrict__ mem)
{
    __shared__ float comb[NK];
    __shared__ int   sidx[NK];
    int b = blockIdx.x, tid = threadIdx.x;

    if (tid < NK) {
        int id = g_idx[(size_t)b * NK + tid];
        sidx[tid] = id;
        float t = g_vals[(size_t)b * NK + tid] + act[(size_t)b * MS + id];
        float m = t;
#pragma unroll
        for (int o = 16; o; o >>= 1) m = fmaxf(m, __shfl_xor_sync(0xffffffffu, m, o));
        float e = expf(t - m);
        float s = e;
#pragma unroll
        for (int o = 16; o; o >>= 1) s += __shfl_xor_sync(0xffffffffu, s, o);
        comb[tid] = e / s;
    }
    __syncthreads();

    for (int h = tid; h < HID; h += 256) {
        float acc = 0.f;
#pragma unroll
        for (int k = 0; k < NK; k++)
            acc += comb[k] * mem[(size_t)sidx[k] * HID + h];
        g_read[(size_t)b * HID + h] = acc;
    }
}

// ---------------------------------------------------------------------------
// Kernel 8: broadcast out[b,s,:] = orow[b,:]
// ---------------------------------------------------------------------------
__global__ void k_broadcast(float* __restrict__ out)
{
    int t = blockIdx.x * blockDim.x + threadIdx.x;   // over BATCH*DIM/4
    if (t < BATCH * DIM / 4) {
        int b = t / (DIM / 4);
        int dq = t % (DIM / 4);
        float4 v = ((const float4*)g_orow)[(size_t)b * (DIM / 4) + dq];
        float4* o = (float4*)out;
#pragma unroll
        for (int s = 0; s < SEQ; s++)
            o[((size_t)b * SEQ + s) * (DIM / 4) + dq] = v;
    }
}

// ---------------------------------------------------------------------------
extern "C" void kernel_launch(void* const* d_in, const int* in_sizes, int n_in,
                              void* d_out, int out_size)
{
    int i = 1;
    // skip scalar 'topk' input if present
    if (in_sizes[1] < 16) i = 2;

    const float* x       = (const float*)d_in[0];
    const float* W_enc   = (const float*)d_in[i++];
    const float* b_enc   = (const float*)d_in[i++];
    const float* w_curv  = (const float*)d_in[i++];
    const float* b_curv  = (const float*)d_in[i++];
    const float* mem     = (const float*)d_in[i++];
    const float* assoc   = (const float*)d_in[i++];
    const float* W_dec   = (const float*)d_in[i++];
    const float* b_dec   = (const float*)d_in[i++];
    const float* temp    = (const float*)d_in[i++];
    float* out = (float*)d_out;

    float* query = nullptr; float* sim = nullptr;
    float* actA = nullptr;  float* actB = nullptr;
    float* readp = nullptr; float* orow = nullptr;
    cudaGetSymbolAddress((void**)&query, g_query);
    cudaGetSymbolAddress((void**)&sim,   g_sim);
    cudaGetSymbolAddress((void**)&actA,  g_actA);
    cudaGetSymbolAddress((void**)&actB,  g_actB);
    cudaGetSymbolAddress((void**)&readp, g_read);
    cudaGetSymbolAddress((void**)&orow,  g_orow);

    // 1. encoder + pooled query
    k_encoder<<<dim3(HID / 128, BATCH), 256>>>(x, W_enc, b_enc, query);
    // 2. sim (raw) = query @ mem^T
    k_gemm_nt<<<dim3(MS / 64, BATCH / 64), 256>>>(query, mem, sim, MS, HID);
    // 3. gate
    k_gate<<<BATCH, 128>>>(query, w_curv, b_curv);
    // 4. top-k on scaled sim
    k_topk<<<BATCH, 256>>>(sim, temp);
    // 5. two rounds of softmax -> @ assoc
    k_softmax<<<BATCH, 256>>>(sim, actA);
    k_gemm_nn<false><<<dim3(MS / 64, BATCH / 64), 256>>>(actA, assoc, actB, MS, MS, nullptr);
    k_softmax<<<BATCH, 256>>>(actB, actA);
    k_gemm_nn<false><<<dim3(MS / 64, BATCH / 64), 256>>>(actA, assoc, actB, MS, MS, nullptr);
    // 6. combine + gather-read
    k_combine<<<BATCH, 256>>>(actB, mem);
    // 7. decoder + tanh
    k_gemm_nn<true><<<dim3(DIM / 64, BATCH / 64), 256>>>(readp, W_dec, orow, DIM, HID, b_dec);
    // 8. broadcast over S
    k_broadcast<<<(BATCH * DIM / 4 + 255) / 256, 256>>>(out);
}

// round 3
// speedup vs baseline: 3.7592x; 3.7592x over previous
#include <cuda_runtime.h>
#include <cuda_bf16.h>
#include <math.h>
#include <float.h>
#include <stdint.h>

#define BATCH 2048
#define SEQ   32
#define DIM   1024
#define HID   1024
#define MS    4096
#define NK    32

typedef __nv_bfloat16 bf16;

// ------------------------------- scratch -----------------------------------
__device__ bf16 g_x3[(size_t)BATCH * SEQ * 2 * DIM];   // [65536][2048] hi|lo
__device__ bf16 g_We3[(size_t)HID * 2 * DIM];          // [1024][2048]  row=h
__device__ bf16 g_mem3[(size_t)MS * 2 * HID];          // [4096][2048]
__device__ bf16 g_as[(size_t)MS * MS];                 // [4096][4096] hi only (row=n)
__device__ bf16 g_Wd3[(size_t)DIM * 2 * HID];          // [1024][2048]  row=d_out
__device__ bf16 g_q3[(size_t)BATCH * 2 * HID];
__device__ bf16 g_act[(size_t)BATCH * MS];             // hi only
__device__ bf16 g_read3[(size_t)BATCH * 2 * HID];
__device__ float g_query[(size_t)BATCH * HID];
__device__ float g_sim[(size_t)BATCH * MS];
__device__ float g_actB[(size_t)BATCH * MS];
__device__ float g_orow[(size_t)BATCH * DIM];
__device__ float g_gate[BATCH];
__device__ float g_vals[BATCH * NK];
__device__ int   g_idx[BATCH * NK];

// ------------------------------ helpers ------------------------------------
__device__ __forceinline__ uint32_t s2u(const void* p) {
    uint32_t a;
    asm("{ .reg .u64 t; cvta.to.shared.u64 t, %1; cvt.u32.u64 %0, t; }" : "=r"(a) : "l"(p));
    return a;
}
__device__ __forceinline__ void cp16(uint32_t d, const void* s) {
    asm volatile("cp.async.cg.shared.global [%0], [%1], 16;\n" :: "r"(d), "l"(s));
}
__device__ __forceinline__ void ldsm4(uint32_t* r, uint32_t a) {
    asm volatile("ldmatrix.sync.aligned.m8n8.x4.shared.b16 {%0,%1,%2,%3}, [%4];"
        : "=r"(r[0]), "=r"(r[1]), "=r"(r[2]), "=r"(r[3]) : "r"(a));
}
__device__ __forceinline__ void ldsm2(uint32_t* r, uint32_t a) {
    asm volatile("ldmatrix.sync.aligned.m8n8.x2.shared.b16 {%0,%1}, [%2];"
        : "=r"(r[0]), "=r"(r[1]) : "r"(a));
}
__device__ __forceinline__ void mma16816(float* c, const uint32_t* a, const uint32_t* b) {
    asm volatile("mma.sync.aligned.m16n8k16.row.col.f32.bf16.bf16.f32 "
        "{%0,%1,%2,%3}, {%4,%5,%6,%7}, {%8,%9}, {%0,%1,%2,%3};"
        : "+f"(c[0]), "+f"(c[1]), "+f"(c[2]), "+f"(c[3])
        : "r"(a[0]), "r"(a[1]), "r"(a[2]), "r"(a[3]), "r"(b[0]), "r"(b[1]));
}
// accurate tanh, 2 MUFU (ex2 + rcp): tanh(x) = sign(x) * (1-t)/(1+t), t=e^{-2|x|}
__device__ __forceinline__ float fast_tanh(float x) {
    float ax = fabsf(x);
    float t = __expf(-2.0f * ax);
    float r = (1.0f - t) / (1.0f + t);
    return copysignf(r, x);
}

// ----------------------------- GEMM ----------------------------------------
// C[M,N] = A @ B^T.   A row-major [m][lda], B row-major [n][ldb].
// terms==3: bf16x3 split — A rows are [hi|lo] (lda=2K), chunk c of 3K/32 maps
//   A segs [hi,lo,hi] / B segs [hi,hi,lo].  terms==1: plain bf16 (lda>=K).
// Tile 128x128, BK=32, 4 smem stages, 8 warps (warp tile 64x32), m16n8k16.
#define PITCH_B 80u        // 40 bf16 per smem row (32 + 8 pad)
#define STAGE_A 10240u     // 128 * 80
#define STAGE_SZ 20480u
#define SMEM_BYTES (4 * STAGE_SZ)

__device__ __forceinline__ void load_chunk(uint32_t sb, int stage, int tid,
    const bf16* __restrict__ A, const bf16* __restrict__ B,
    int lda, int ldb, int m0, int n0, int K, int c)
{
    int off = c * 32;
    int aoff = (off >= 2 * K) ? off - 2 * K : off;
    int boff = (off >= K)     ? off - K     : off;
    const bf16* Ag = A + (size_t)m0 * lda + aoff;
    const bf16* Bg = B + (size_t)n0 * ldb + boff;
    uint32_t base = sb + (uint32_t)stage * STAGE_SZ;
#pragma unroll
    for (int t = 0; t < 2; t++) {
        int idx = tid + t * 256;          // 0..511
        int row = idx >> 2, seg = idx & 3;
        cp16(base + row * PITCH_B + seg * 16u, Ag + (size_t)row * lda + seg * 8);
        cp16(base + STAGE_A + row * PITCH_B + seg * 16u, Bg + (size_t)row * ldb + seg * 8);
    }
    asm volatile("cp.async.commit_group;\n" ::: "memory");
}

template <int EPI>   // 0 = fp32 store; 1 = encoder tanh+bias+mean epilogue
__global__ void __launch_bounds__(256, 2)
k_mmagemm(const bf16* __restrict__ A, const bf16* __restrict__ B,
          int lda, int ldb, int K, int terms,
          float* __restrict__ C, int Nst,
          const float* __restrict__ bias,
          float* __restrict__ qout, bf16* __restrict__ q3out)
{
    extern __shared__ char smem[];
    const uint32_t sb = s2u(smem);
    const int tid = threadIdx.x, wid = tid >> 5, lane = tid & 31;
    const int wr = wid >> 2, wc = wid & 3;          // warp grid 2x4
    const int m0 = blockIdx.y * 128, n0 = blockIdx.x * 128;
    const int NC = terms * K / 32;

    float acc[4][4][4];
#pragma unroll
    for (int a = 0; a < 4; a++)
#pragma unroll
        for (int b = 0; b < 4; b++)
#pragma unroll
            for (int c = 0; c < 4; c++) acc[a][b][c] = 0.f;

    load_chunk(sb, 0, tid, A, B, lda, ldb, m0, n0, K, 0);
    load_chunk(sb, 1, tid, A, B, lda, ldb, m0, n0, K, 1);
    load_chunk(sb, 2, tid, A, B, lda, ldb, m0, n0, K, 2);

    for (int c = 0; c < NC; c++) {
        int rem = NC - 1 - c;
        if (rem >= 2)      asm volatile("cp.async.wait_group 2;\n" ::: "memory");
        else if (rem == 1) asm volatile("cp.async.wait_group 1;\n" ::: "memory");
        else               asm volatile("cp.async.wait_group 0;\n" ::: "memory");
        __syncthreads();

        const uint32_t As = sb + (uint32_t)(c & 3) * STAGE_SZ;
        const uint32_t Bs = As + STAGE_A;
#pragma unroll
        for (int ks = 0; ks < 2; ks++) {
            uint32_t af[4][4], bfr[4][2];
            uint32_t abase = As + (uint32_t)(wr * 64 + (lane & 15)) * PITCH_B
                           + ks * 32u + (uint32_t)(lane >> 4) * 16u;
#pragma unroll
            for (int mi = 0; mi < 4; mi++) ldsm4(af[mi], abase + mi * 16u * PITCH_B);
            uint32_t bbase = Bs + (uint32_t)(wc * 32 + (lane & 7)) * PITCH_B
                           + ks * 32u + (uint32_t)((lane >> 3) & 1) * 16u;
#pragma unroll
            for (int ni = 0; ni < 4; ni++) ldsm2(bfr[ni], bbase + ni * 8u * PITCH_B);
#pragma unroll
            for (int mi = 0; mi < 4; mi++)
#pragma unroll
                for (int ni = 0; ni < 4; ni++) mma16816(acc[mi][ni], af[mi], bfr[ni]);
        }
        if (c + 3 < NC) {
            __syncthreads();   // compute of stage (c+3)&3 (done at iter c-1) fully drained
            load_chunk(sb, (c + 3) & 3, tid, A, B, lda, ldb, m0, n0, K, c + 3);
        }
    }

    if (EPI == 0) {
#pragma unroll
        for (int mi = 0; mi < 4; mi++) {
            int r = m0 + wr * 64 + mi * 16 + (lane >> 2);
#pragma unroll
            for (int ni = 0; ni < 4; ni++) {
                int col = n0 + wc * 32 + ni * 8 + 2 * (lane & 3);
                float2 v0 = make_float2(acc[mi][ni][0], acc[mi][ni][1]);
                float2 v1 = make_float2(acc[mi][ni][2], acc[mi][ni][3]);
                *(float2*)&C[(size_t)r * Nst + col] = v0;
                *(float2*)&C[(size_t)(r + 8) * Nst + col] = v1;
            }
        }
    } else {
        // rows are batch*SEQ; each 32-row group = one batch. warp holds 2 batches.
#pragma unroll
        for (int b = 0; b < 2; b++) {
            int batch = m0 / 32 + wr * 2 + b;
#pragma unroll
            for (int ni = 0; ni < 4; ni++) {
                int col0 = n0 + wc * 32 + ni * 8 + 2 * (lane & 3);
                float bi0 = bias[col0], bi1 = bias[col0 + 1];
                float s0 = 0.f, s1 = 0.f;
#pragma unroll
                for (int mh = 0; mh < 2; mh++) {
                    float* cc = acc[b * 2 + mh][ni];
                    s0 += fast_tanh(cc[0] + bi0) + fast_tanh(cc[2] + bi0);
                    s1 += fast_tanh(cc[1] + bi1) + fast_tanh(cc[3] + bi1);
                }
#pragma unroll
                for (int o = 4; o <= 16; o <<= 1) {
                    s0 += __shfl_xor_sync(0xffffffffu, s0, o);
                    s1 += __shfl_xor_sync(0xffffffffu, s1, o);
                }
                if (lane < 4) {
                    float q0 = s0 * (1.0f / SEQ), q1 = s1 * (1.0f / SEQ);
                    qout[(size_t)batch * HID + col0] = q0;
                    qout[(size_t)batch * HID + col0 + 1] = q1;
                    bf16 h0 = __float2bfloat16(q0);
                    bf16 l0 = __float2bfloat16(q0 - __bfloat162float(h0));
                    bf16 h1 = __float2bfloat16(q1);
                    bf16 l1 = __float2bfloat16(q1 - __bfloat162float(h1));
                    size_t rb = (size_t)batch * (2 * HID);
                    q3out[rb + col0] = h0;       q3out[rb + col0 + 1] = h1;
                    q3out[rb + HID + col0] = l0; q3out[rb + HID + col0 + 1] = l1;
                }
            }
        }
    }
}

// ---------------------- decomposition kernels ------------------------------
__global__ void k_dec(const float* __restrict__ in, bf16* __restrict__ out,
                      int K, long total4)
{
    long t = (long)blockIdx.x * 256 + threadIdx.x;
    if (t >= total4) return;
    long r = t / (K / 4);
    int  c = (int)(t % (K / 4)) * 4;
    float4 v = *(const float4*)(in + r * K + c);
    bf16 h0 = __float2bfloat16(v.x), h1 = __float2bfloat16(v.y);
    bf16 h2 = __float2bfloat16(v.z), h3 = __float2bfloat16(v.w);
    bf16 l0 = __float2bfloat16(v.x - __bfloat162float(h0));
    bf16 l1 = __float2bfloat16(v.y - __bfloat162float(h1));
    bf16 l2 = __float2bfloat16(v.z - __bfloat162float(h2));
    bf16 l3 = __float2bfloat16(v.w - __bfloat162float(h3));
    __nv_bfloat162* oh = (__nv_bfloat162*)(out + r * (2L * K) + c);
    __nv_bfloat162* ol = (__nv_bfloat162*)(out + r * (2L * K) + K + c);
    __nv_bfloat162 p;
    p.x = h0; p.y = h1; oh[0] = p;  p.x = h2; p.y = h3; oh[1] = p;
    p.x = l0; p.y = l1; ol[0] = p;  p.x = l2; p.y = l3; ol[1] = p;
}

// transpose + hi|lo:  fp32 [K,N] -> bf16 [N][2K]
__global__ void k_tdec(const float* __restrict__ in, bf16* __restrict__ out,
                       int K, int N)
{
    __shared__ float tile[32][33];
    int n0 = blockIdx.x * 32, k0 = blockIdx.y * 32;
    int tx = threadIdx.x & 31, ty = threadIdx.x >> 5;
    for (int r = ty; r < 32; r += 8)
        tile[r][tx] = in[(size_t)(k0 + r) * N + n0 + tx];
    __syncthreads();
    for (int r = ty; r < 32; r += 8) {
        float v = tile[tx][r];
        bf16 hi = __float2bfloat16(v);
        bf16 lo = __float2bfloat16(v - __bfloat162float(hi));
        size_t base = (size_t)(n0 + r) * (2 * K);
        out[base + k0 + tx] = hi;
        out[base + K + k0 + tx] = lo;
    }
}

// transpose, hi only:  fp32 [K,N] -> bf16 [N][K]
__global__ void k_tdec1(const float* __restrict__ in, bf16* __restrict__ out,
                        int K, int N)
{
    __shared__ float tile[32][33];
    int n0 = blockIdx.x * 32, k0 = blockIdx.y * 32;
    int tx = threadIdx.x & 31, ty = threadIdx.x >> 5;
    for (int r = ty; r < 32; r += 8)
        tile[r][tx] = in[(size_t)(k0 + r) * N + n0 + tx];
    __syncthreads();
    for (int r = ty; r < 32; r += 8)
        out[(size_t)(n0 + r) * K + k0 + tx] = __float2bfloat16(tile[tx][r]);
}

// ------------------------------ gate ---------------------------------------
__global__ void k_gate(const float* __restrict__ query,
                       const float* __restrict__ w_curv,
                       const float* __restrict__ b_curv)
{
    __shared__ float red[4];
    int b = blockIdx.x, tid = threadIdx.x;
    float s = 0.f;
    for (int h = tid; h < HID; h += 128)
        s += query[(size_t)b * HID + h] * w_curv[h];
#pragma unroll
    for (int o = 16; o; o >>= 1) s += __shfl_xor_sync(0xffffffffu, s, o);
    if ((tid & 31) == 0) red[tid >> 5] = s;
    __syncthreads();
    if (tid == 0) {
        float t = red[0] + red[1] + red[2] + red[3] + b_curv[0];
        g_gate[b] = 1.0f / (1.0f + expf(-t));
    }
}

// ------------------------------ top-k --------------------------------------
__global__ void k_topk(const float* __restrict__ sim,
                       const float* __restrict__ temperature)
{
    __shared__ float sv[MS];
    __shared__ float rv[256];
    __shared__ int   ri[256];
    int b = blockIdx.x, tid = threadIdx.x;
    float scale = (0.5f + g_gate[b]) / fmaxf(temperature[0], 1e-6f);
    const float* row = sim + (size_t)b * MS;
    for (int i = tid; i < MS; i += 256) sv[i] = row[i] * scale;
    __syncthreads();
    for (int k = 0; k < NK; k++) {
        float bv = -FLT_MAX; int bi = MS;
        for (int i = tid; i < MS; i += 256) {
            float v = sv[i];
            if (v > bv || (v == bv && i < bi)) { bv = v; bi = i; }
        }
        rv[tid] = bv; ri[tid] = bi;
        __syncthreads();
        for (int off = 128; off; off >>= 1) {
            if (tid < off) {
                float v2 = rv[tid + off]; int i2 = ri[tid + off];
                if (v2 > rv[tid] || (v2 == rv[tid] && i2 < ri[tid])) { rv[tid] = v2; ri[tid] = i2; }
            }
            __syncthreads();
        }
        if (tid == 0) {
            g_vals[(size_t)b * NK + k] = rv[0];
            g_idx [(size_t)b * NK + k] = ri[0];
            sv[ri[0]] = -FLT_MAX;
        }
        __syncthreads();
    }
}

// --------------- softmax over M=4096 -> bf16 (hi only) ----------------------
__global__ void k_softmax_dec(const float* __restrict__ in, bf16* __restrict__ out)
{
    __shared__ float sv[MS];
    __shared__ float red[256];
    int b = blockIdx.x, tid = threadIdx.x;
    const float* row = in + (size_t)b * MS;
    float mx = -FLT_MAX;
    for (int i = tid; i < MS; i += 256) { float v = row[i]; sv[i] = v; mx = fmaxf(mx, v); }
    red[tid] = mx; __syncthreads();
    for (int off = 128; off; off >>= 1) { if (tid < off) red[tid] = fmaxf(red[tid], red[tid + off]); __syncthreads(); }
    mx = red[0]; __syncthreads();
    float s = 0.f;
    for (int i = tid; i < MS; i += 256) { float e = expf(sv[i] - mx); sv[i] = e; s += e; }
    red[tid] = s; __syncthreads();
    for (int off = 128; off; off >>= 1) { if (tid < off) red[tid] += red[tid + off]; __syncthreads(); }
    float inv = 1.0f / red[0];
    bf16* orow = out + (size_t)b * MS;
    for (int i = tid; i < MS; i += 256)
        orow[i] = __float2bfloat16(sv[i] * inv);
}

// ------- combine: softmax(vals + act[idx]) then read = comb @ mem[idx] -----
__global__ void k_combine(const float* __restrict__ act,
                          const float* __restrict__ mem)
{
    __shared__ float comb[NK];
    __shared__ int   sidx[NK];
    int b = blockIdx.x, tid = threadIdx.x;
    if (tid < NK) {
        int id = g_idx[(size_t)b * NK + tid];
        sidx[tid] = id;
        float t = g_vals[(size_t)b * NK + tid] + act[(size_t)b * MS + id];
        float m = t;
#pragma unroll
        for (int o = 16; o; o >>= 1) m = fmaxf(m, __shfl_xor_sync(0xffffffffu, m, o));
        float e = expf(t - m);
        float s = e;
#pragma unroll
        for (int o = 16; o; o >>= 1) s += __shfl_xor_sync(0xffffffffu, s, o);
        comb[tid] = e / s;
    }
    __syncthreads();
    for (int h = tid; h < HID; h += 256) {
        float acc = 0.f;
#pragma unroll
        for (int k = 0; k < NK; k++)
            acc += comb[k] * mem[(size_t)sidx[k] * HID + h];
        bf16 hi = __float2bfloat16(acc);
        bf16 lo = __float2bfloat16(acc - __bfloat162float(hi));
        g_read3[(size_t)b * (2 * HID) + h] = hi;
        g_read3[(size_t)b * (2 * HID) + HID + h] = lo;
    }
}

// --------------- broadcast: out[b,s,:] = tanh(orow + b_dec) ----------------
__global__ void k_broadcast(const float* __restrict__ orow,
                            const float* __restrict__ bdec,
                            float* __restrict__ out)
{
    int t = blockIdx.x * blockDim.x + threadIdx.x;
    if (t < BATCH * DIM / 4) {
        int b = t / (DIM / 4), dq = t % (DIM / 4);
        float4 v = ((const float4*)orow)[(size_t)b * (DIM / 4) + dq];
        float4 bb = ((const float4*)bdec)[dq];
        v.x = tanhf(v.x + bb.x); v.y = tanhf(v.y + bb.y);
        v.z = tanhf(v.z + bb.z); v.w = tanhf(v.w + bb.w);
        float4* o = (float4*)out;
#pragma unroll
        for (int s = 0; s < SEQ; s++)
            o[((size_t)b * SEQ + s) * (DIM / 4) + dq] = v;
    }
}

// ---------------------------------------------------------------------------
extern "C" void kernel_launch(void* const* d_in, const int* in_sizes, int n_in,
                              void* d_out, int out_size)
{
    int i = 1;
    if (in_sizes[1] < 16) i = 2;   // skip scalar 'topk' input if present

    const float* x      = (const float*)d_in[0];
    const float* W_enc  = (const float*)d_in[i++];
    const float* b_enc  = (const float*)d_in[i++];
    const float* w_curv = (const float*)d_in[i++];
    const float* b_curv = (const float*)d_in[i++];
    const float* mem    = (const float*)d_in[i++];
    const float* assoc  = (const float*)d_in[i++];
    const float* W_dec  = (const float*)d_in[i++];
    const float* b_dec  = (const float*)d_in[i++];
    const float* temp   = (const float*)d_in[i++];
    float* out = (float*)d_out;

    bf16 *x3, *We3, *mem3, *as1, *Wd3, *q3, *act1, *read3;
    float *query, *sim, *actB, *orow;
    cudaGetSymbolAddress((void**)&x3,    g_x3);
    cudaGetSymbolAddress((void**)&We3,   g_We3);
    cudaGetSymbolAddress((void**)&mem3,  g_mem3);
    cudaGetSymbolAddress((void**)&as1,   g_as);
    cudaGetSymbolAddress((void**)&Wd3,   g_Wd3);
    cudaGetSymbolAddress((void**)&q3,    g_q3);
    cudaGetSymbolAddress((void**)&act1,  g_act);
    cudaGetSymbolAddress((void**)&read3, g_read3);
    cudaGetSymbolAddress((void**)&query, g_query);
    cudaGetSymbolAddress((void**)&sim,   g_sim);
    cudaGetSymbolAddress((void**)&actB,  g_actB);
    cudaGetSymbolAddress((void**)&orow,  g_orow);

    cudaFuncSetAttribute(k_mmagemm<0>, cudaFuncAttributeMaxDynamicSharedMemorySize, SMEM_BYTES);
    cudaFuncSetAttribute(k_mmagemm<1>, cudaFuncAttributeMaxDynamicSharedMemorySize, SMEM_BYTES);

    // ---- decompositions ----
    k_dec<<<(int)((long)BATCH * SEQ * DIM / 4 / 256), 256>>>(x, x3, DIM, (long)BATCH * SEQ * DIM / 4);
    k_dec<<<(int)((long)MS * HID / 4 / 256), 256>>>(mem, mem3, HID, (long)MS * HID / 4);
    k_tdec<<<dim3(HID / 32, DIM / 32), 256>>>(W_enc, We3, DIM, HID);
    k_tdec1<<<dim3(MS / 32, MS / 32), 256>>>(assoc, as1, MS, MS);
    k_tdec<<<dim3(DIM / 32, HID / 32), 256>>>(W_dec, Wd3, HID, DIM);

    // ---- encoder GEMM (bf16x3) + fused tanh/bias/mean -> query + q3 ----
    k_mmagemm<1><<<dim3(HID / 128, BATCH * SEQ / 128), 256, SMEM_BYTES>>>(
        x3, We3, 2 * DIM, 2 * DIM, DIM, 3, nullptr, 0, b_enc, query, q3);
    // ---- gate ----
    k_gate<<<BATCH, 128>>>(query, w_curv, b_curv);
    // ---- sim = query @ mem^T (bf16x3) ----
    k_mmagemm<0><<<dim3(MS / 128, BATCH / 128), 256, SMEM_BYTES>>>(
        q3, mem3, 2 * HID, 2 * HID, HID, 3, sim, MS, nullptr, nullptr, nullptr);
    // ---- top-k on scaled sim ----
    k_topk<<<BATCH, 256>>>(sim, temp);
    // ---- two rounds of softmax -> @ assoc (plain bf16) ----
    k_softmax_dec<<<BATCH, 256>>>(sim, act1);
    k_mmagemm<0><<<dim3(MS / 128, BATCH / 128), 256, SMEM_BYTES>>>(
        act1, as1, MS, MS, MS, 1, actB, MS, nullptr, nullptr, nullptr);
    k_softmax_dec<<<BATCH, 256>>>(actB, act1);
    k_mmagemm<0><<<dim3(MS / 128, BATCH / 128), 256, SMEM_BYTES>>>(
        act1, as1, MS, MS, MS, 1, actB, MS, nullptr, nullptr, nullptr);
    // ---- combine + gather-read (-> bf16 hi|lo) ----
    k_combine<<<BATCH, 256>>>(actB, mem);
    // ---- decoder GEMM (bf16x3) ----
    k_mmagemm<0><<<dim3(DIM / 128, BATCH / 128), 256, SMEM_BYTES>>>(
        read3, Wd3, 2 * HID, 2 * HID, HID, 3, orow, DIM, nullptr, nullptr, nullptr);
    // ---- bias + tanh + broadcast over S ----
    k_broadcast<<<(BATCH * DIM / 4 + 255) / 256, 256>>>(orow, b_dec, out);
}

// round 4
// speedup vs baseline: 4.7520x; 1.2641x over previous
#include <cuda_runtime.h>
#include <cuda_bf16.h>
#include <math.h>
#include <float.h>
#include <stdint.h>

#define BATCH 2048
#define SEQ   32
#define DIM   1024
#define HID   1024
#define MS    4096
#define NK    32

typedef __nv_bfloat16 bf16;

// Tiled layout: tile = 128 rows x 64 cols bf16 = 16KB, SW128-swizzled.
// Matrix [R][2K or K] stored as tiles [rb][kb][8192 elems].
#define TILE_E 8192
#define TILE_B 16384

// ------------------------------- scratch -----------------------------------
__device__ bf16 g_x3[(size_t)BATCH * SEQ * 2 * DIM];   // tiled [512][32]
__device__ bf16 g_We3[(size_t)HID * 2 * DIM];          // tiled [8][32]
__device__ bf16 g_mem3[(size_t)MS * 2 * HID];          // tiled [32][32]
__device__ bf16 g_as[(size_t)MS * MS];                 // tiled [32][64] hi-only
__device__ bf16 g_Wd3[(size_t)DIM * 2 * HID];          // tiled [8][32]
__device__ bf16 g_q3[(size_t)BATCH * 2 * HID];         // tiled [16][32]
__device__ bf16 g_act[(size_t)BATCH * MS];             // tiled [16][64] hi-only
__device__ bf16 g_read3[(size_t)BATCH * 2 * HID];      // tiled [16][32]
__device__ float g_query[(size_t)BATCH * HID];
__device__ float g_sim[(size_t)BATCH * MS];
__device__ float g_actB[(size_t)BATCH * MS];
__device__ float g_orow[(size_t)BATCH * DIM];
__device__ float g_gate[BATCH];
__device__ float g_vals[BATCH * NK];
__device__ int   g_idx[BATCH * NK];

// ------------------------------ helpers ------------------------------------
__device__ __forceinline__ uint32_t s2u(const void* p) {
    uint32_t a;
    asm("{ .reg .u64 t; cvta.to.shared.u64 t, %1; cvt.u32.u64 %0, t; }" : "=r"(a) : "l"(p));
    return a;
}
__device__ __forceinline__ uint32_t swz(uint32_t lin) {
    return lin ^ ((lin >> 3) & 0x70u);
}
__device__ __forceinline__ void ldsm4(uint32_t* r, uint32_t a) {
    asm volatile("ldmatrix.sync.aligned.m8n8.x4.shared.b16 {%0,%1,%2,%3}, [%4];"
        : "=r"(r[0]), "=r"(r[1]), "=r"(r[2]), "=r"(r[3]) : "r"(a));
}
__device__ __forceinline__ void ldsm2(uint32_t* r, uint32_t a) {
    asm volatile("ldmatrix.sync.aligned.m8n8.x2.shared.b16 {%0,%1}, [%2];"
        : "=r"(r[0]), "=r"(r[1]) : "r"(a));
}
__device__ __forceinline__ void mma16816(float* c, const uint32_t* a, const uint32_t* b) {
    asm volatile("mma.sync.aligned.m16n8k16.row.col.f32.bf16.bf16.f32 "
        "{%0,%1,%2,%3}, {%4,%5,%6,%7}, {%8,%9}, {%0,%1,%2,%3};"
        : "+f"(c[0]), "+f"(c[1]), "+f"(c[2]), "+f"(c[3])
        : "r"(a[0]), "r"(a[1]), "r"(a[2]), "r"(a[3]), "r"(b[0]), "r"(b[1]));
}
__device__ __forceinline__ float fast_tanh(float x) {
    float ax = fabsf(x);
    float t = __expf(-2.0f * ax);
    float r = (1.0f - t) / (1.0f + t);
    return copysignf(r, x);
}
__device__ __forceinline__ uint32_t pk2(float a, float b) {
    __nv_bfloat162 h;
    h.x = __float2bfloat16(a); h.y = __float2bfloat16(b);
    return *(uint32_t*)&h;
}

#define MBARRIER_INIT(mb, c) \
    asm volatile("mbarrier.init.shared.b64 [%0], %1;" :: "r"((uint32_t)(mb)), "r"((uint32_t)(c)) : "memory")
#define MBAR_ARRIVE_EXPECT(mb, tx) \
    asm volatile("mbarrier.arrive.expect_tx.shared.b64 _, [%0], %1;" :: "r"((uint32_t)(mb)), "r"((uint32_t)(tx)) : "memory")
#define BULK_G2S(dst, src, bytes, mb) \
    asm volatile("cp.async.bulk.shared::cluster.global.mbarrier::complete_tx::bytes [%0], [%1], %2, [%3];" \
        :: "r"((uint32_t)(dst)), "l"(src), "r"((uint32_t)(bytes)), "r"((uint32_t)(mb)) : "memory")
#define MBARRIER_WAIT_PARITY(mb, ph) do {                                              \
    uint32_t _mb = (uint32_t)(mb); uint32_t _ph = (uint32_t)(ph); uint32_t _done;      \
    asm volatile("{\n .reg .pred p;\n"                                                 \
        " mbarrier.try_wait.parity.acquire.cta.shared::cta.b64 p, [%1], %2;\n"         \
        " selp.b32 %0, 1, 0, p;\n}"                                                    \
        : "=r"(_done) : "r"(_mb), "r"(_ph) : "memory");                                \
    if (!_done) {                                                                      \
        asm volatile("{\n .reg .pred P1;\n"                                            \
            "WL_%=:\n"                                                                 \
            " mbarrier.try_wait.parity.acquire.cta.shared::cta.b64 P1, [%0], %1, 0x989680;\n" \
            " @P1 bra.uni WD_%=;\n bra.uni WL_%=;\nWD_%=:\n}"                          \
            :: "r"(_mb), "r"(_ph) : "memory");                                         \
    }                                                                                  \
} while (0)

// ----------------------------- GEMM ----------------------------------------
// C[M,N] = A @ B^T, A/B in tiled-swizzled bf16 layout.
// BM=256, BN=128, BK=64. 512 threads, 16 warps as 4(row)x4(col), warp 64x32.
// terms==3 (bf16x3, K tripled w/ segment remap) or terms==1 (plain bf16).
// 4 stages; per chunk: 3 cp.async.bulk (2 A tiles + 1 B tile) -> mbarrier.
#define NSTAGE 4
#define STG_SZ 49152u    // 2*16KB A + 16KB B
#define SMEM_BYTES (1024 + NSTAGE * 49152)

template <int EPI>   // 0 = fp32 store; 1 = encoder tanh+bias+mean epilogue
__global__ void __launch_bounds__(512, 1)
k_gemm(const bf16* __restrict__ A, const bf16* __restrict__ B,
       int nkbA, int nkbB, int K, int terms,
       float* __restrict__ C, int Nst,
       const float* __restrict__ bias,
       float* __restrict__ qout, bf16* __restrict__ q3out)
{
    extern __shared__ char smem[];
    const uint32_t sb = s2u(smem);
    const int tid = threadIdx.x, wid = tid >> 5, lane = tid & 31;
    const int wr = wid >> 2, wc = wid & 3;          // 4x4 warp grid
    const int m0 = blockIdx.y * 256, n0 = blockIdx.x * 128;
    const int Kb = K / 64;
    const int NC = terms * Kb;

    // init barriers
    if (tid == 0) {
#pragma unroll
        for (int s = 0; s < NSTAGE; s++) MBARRIER_INIT(sb + s * 8, 1);
    }
    __syncthreads();

    // precomputed (lane-const) unswizzled lin offsets
    const int rA = (wr * 64) & 127;                  // row within 128-tile
    const uint32_t aTileSel = (wr >= 2) ? TILE_B : 0u;
    uint32_t alin[4], blin[4];
#pragma unroll
    for (int mi = 0; mi < 4; mi++)
        alin[mi] = (uint32_t)(rA + mi * 16 + (lane & 15)) * 128u + (uint32_t)(lane >> 4) * 16u;
#pragma unroll
    for (int ni = 0; ni < 4; ni++)
        blin[ni] = (uint32_t)(wc * 32 + ni * 8 + (lane & 7)) * 128u + (uint32_t)((lane >> 3) & 1) * 16u;

    float acc[4][4][4];
#pragma unroll
    for (int a = 0; a < 4; a++)
#pragma unroll
        for (int b = 0; b < 4; b++)
#pragma unroll
            for (int c = 0; c < 4; c++) acc[a][b][c] = 0.f;

    const int rbA0 = blockIdx.y * 2;
    // issue chunks 0..2
    if (tid == 0) {
#pragma unroll
        for (int c0 = 0; c0 < 3; c0++) {
            int akb = (terms == 3) ? ((c0 < 2 * Kb) ? c0 : c0 - 2 * Kb) : c0;
            int bkb = (terms == 3) ? ((c0 < Kb) ? c0 : c0 - Kb) : c0;
            uint32_t mb = sb + (uint32_t)c0 * 8;
            uint32_t dst = sb + 1024u + (uint32_t)c0 * STG_SZ;
            MBAR_ARRIVE_EXPECT(mb, STG_SZ);
            BULK_G2S(dst,               A + ((size_t)rbA0 * nkbA + akb) * TILE_E, TILE_B, mb);
            BULK_G2S(dst + TILE_B,      A + ((size_t)(rbA0 + 1) * nkbA + akb) * TILE_E, TILE_B, mb);
            BULK_G2S(dst + 2 * TILE_B,  B + ((size_t)blockIdx.x * nkbB + bkb) * TILE_E, TILE_B, mb);
        }
    }

    for (int c = 0; c < NC; c++) {
        int s = c & (NSTAGE - 1);
        MBARRIER_WAIT_PARITY(sb + s * 8, (c >> 2) & 1);

        const uint32_t As = sb + 1024u + (uint32_t)s * STG_SZ + aTileSel;
        const uint32_t Bs = sb + 1024u + (uint32_t)s * STG_SZ + 2u * TILE_B;
#pragma unroll
        for (int ks = 0; ks < 4; ks++) {
            uint32_t af[4][4], bfr[4][2];
#pragma unroll
            for (int mi = 0; mi < 4; mi++) ldsm4(af[mi], As + swz(alin[mi] + ks * 32u));
#pragma unroll
            for (int ni = 0; ni < 4; ni++) ldsm2(bfr[ni], Bs + swz(blin[ni] + ks * 32u));
#pragma unroll
            for (int mi = 0; mi < 4; mi++)
#pragma unroll
                for (int ni = 0; ni < 4; ni++) mma16816(acc[mi][ni], af[mi], bfr[ni]);
        }
        __syncthreads();   // all warps done with stage s' = (c+3)&3 (used at c-1)
        if (c + 3 < NC && tid == 0) {
            int cn = c + 3;
            int akb = (terms == 3) ? ((cn < 2 * Kb) ? cn : cn - 2 * Kb) : cn;
            int bkb = (terms == 3) ? ((cn < Kb) ? cn : cn - Kb) : cn;
            int sn = cn & (NSTAGE - 1);
            uint32_t mb = sb + (uint32_t)sn * 8;
            uint32_t dst = sb + 1024u + (uint32_t)sn * STG_SZ;
            MBAR_ARRIVE_EXPECT(mb, STG_SZ);
            BULK_G2S(dst,              A + ((size_t)rbA0 * nkbA + akb) * TILE_E, TILE_B, mb);
            BULK_G2S(dst + TILE_B,     A + ((size_t)(rbA0 + 1) * nkbA + akb) * TILE_E, TILE_B, mb);
            BULK_G2S(dst + 2 * TILE_B, B + ((size_t)blockIdx.x * nkbB + bkb) * TILE_E, TILE_B, mb);
        }
    }

    if (EPI == 0) {
#pragma unroll
        for (int mi = 0; mi < 4; mi++) {
            int r = m0 + wr * 64 + mi * 16 + (lane >> 2);
#pragma unroll
            for (int ni = 0; ni < 4; ni++) {
                int col = n0 + wc * 32 + ni * 8 + 2 * (lane & 3);
                *(float2*)&C[(size_t)r * Nst + col] = make_float2(acc[mi][ni][0], acc[mi][ni][1]);
                *(float2*)&C[(size_t)(r + 8) * Nst + col] = make_float2(acc[mi][ni][2], acc[mi][ni][3]);
            }
        }
    } else {
        // rows = batch*SEQ; 32-row group = one batch; warp holds 2 batches.
#pragma unroll
        for (int b = 0; b < 2; b++) {
            int batch = m0 / 32 + wr * 2 + b;
#pragma unroll
            for (int ni = 0; ni < 4; ni++) {
                int col0 = n0 + wc * 32 + ni * 8 + 2 * (lane & 3);
                float bi0 = bias[col0], bi1 = bias[col0 + 1];
                float s0 = 0.f, s1 = 0.f;
#pragma unroll
                for (int mh = 0; mh < 2; mh++) {
                    float* cc = acc[b * 2 + mh][ni];
                    s0 += fast_tanh(cc[0] + bi0) + fast_tanh(cc[2] + bi0);
                    s1 += fast_tanh(cc[1] + bi1) + fast_tanh(cc[3] + bi1);
                }
#pragma unroll
                for (int o = 4; o <= 16; o <<= 1) {
                    s0 += __shfl_xor_sync(0xffffffffu, s0, o);
                    s1 += __shfl_xor_sync(0xffffffffu, s1, o);
                }
                if (lane < 4) {
                    float q0 = s0 * (1.0f / SEQ), q1 = s1 * (1.0f / SEQ);
                    qout[(size_t)batch * HID + col0] = q0;
                    qout[(size_t)batch * HID + col0 + 1] = q1;
                    // q3 tiled write (hi at kb, lo at kb+HID/64)
                    uint32_t lin = swz(((uint32_t)(batch & 127) << 7) + ((uint32_t)(col0 & 63) << 1));
                    int rb = batch >> 7, kb = col0 >> 6;
                    char* th = (char*)q3out + ((size_t)rb * (2 * HID / 64) + kb) * TILE_B + lin;
                    char* tl = (char*)q3out + ((size_t)rb * (2 * HID / 64) + kb + HID / 64) * TILE_B + lin;
                    bf16 h0 = __float2bfloat16(q0), h1 = __float2bfloat16(q1);
                    *(uint32_t*)th = pk2(q0, q1);
                    *(uint32_t*)tl = pk2(q0 - __bfloat162float(h0), q1 - __bfloat162float(h1));
                }
            }
        }
    }
}

// ---------------------- prep: row-major fp32 -> tiled hi|lo ----------------
__global__ void k_dec_t(const float* __restrict__ in, bf16* __restrict__ out,
                        int K, long nGran)
{
    long g = (long)blockIdx.x * 256 + threadIdx.x;
    if (g >= nGran) return;
    int perRow = K / 8;
    long r = g / perRow;
    int c = (int)(g % perRow) * 8;
    float4 v0 = *(const float4*)(in + r * K + c);
    float4 v1 = *(const float4*)(in + r * K + c + 4);
    float f[8] = {v0.x, v0.y, v0.z, v0.w, v1.x, v1.y, v1.z, v1.w};
    uint32_t hi[4], lo[4];
#pragma unroll
    for (int j = 0; j < 4; j++) {
        bf16 h0 = __float2bfloat16(f[2 * j]), h1 = __float2bfloat16(f[2 * j + 1]);
        __nv_bfloat162 hp; hp.x = h0; hp.y = h1;
        hi[j] = *(uint32_t*)&hp;
        lo[j] = pk2(f[2 * j] - __bfloat162float(h0), f[2 * j + 1] - __bfloat162float(h1));
    }
    int rb = (int)(r >> 7), kb = c >> 6, kbT = 2 * K / 64;
    uint32_t lin = swz(((uint32_t)(r & 127) << 7) + ((uint32_t)(c & 63) << 1));
    *(uint4*)((char*)out + ((size_t)rb * kbT + kb) * TILE_B + lin) = make_uint4(hi[0], hi[1], hi[2], hi[3]);
    *(uint4*)((char*)out + ((size_t)rb * kbT + kb + K / 64) * TILE_B + lin) = make_uint4(lo[0], lo[1], lo[2], lo[3]);
}

// ------------- prep: transpose fp32 [K][N] -> tiled rows=n ------------------
template <bool LO>
__global__ void k_tdec_t(const float* __restrict__ in, bf16* __restrict__ out,
                         int K, int N)
{
    __shared__ float tile[32][33];
    int n0 = blockIdx.x * 32, k0 = blockIdx.y * 32;
    int tx = threadIdx.x & 31, ty = threadIdx.x >> 5;
    for (int r = ty; r < 32; r += 8)
        tile[r][tx] = in[(size_t)(k0 + r) * N + n0 + tx];
    __syncthreads();
    int t = threadIdx.x;
    if (t < 128) {
        int nl = t & 31, kg = t >> 5;                 // kg 0..3
        float f[8];
#pragma unroll
        for (int j = 0; j < 8; j++) f[j] = tile[kg * 8 + j][nl];
        int n = n0 + nl, k = k0 + kg * 8;
        uint32_t hi[4], lo[4];
#pragma unroll
        for (int j = 0; j < 4; j++) {
            bf16 h0 = __float2bfloat16(f[2 * j]), h1 = __float2bfloat16(f[2 * j + 1]);
            __nv_bfloat162 hp; hp.x = h0; hp.y = h1;
            hi[j] = *(uint32_t*)&hp;
            if (LO)
                lo[j] = pk2(f[2 * j] - __bfloat162float(h0), f[2 * j + 1] - __bfloat162float(h1));
        }
        int rb = n >> 7, kb = k >> 6;
        int kbT = LO ? 2 * K / 64 : K / 64;
        uint32_t lin = swz(((uint32_t)(n & 127) << 7) + ((uint32_t)(k & 63) << 1));
        *(uint4*)((char*)out + ((size_t)rb * kbT + kb) * TILE_B + lin) = make_uint4(hi[0], hi[1], hi[2], hi[3]);
        if (LO)
            *(uint4*)((char*)out + ((size_t)rb * kbT + kb + K / 64) * TILE_B + lin) = make_uint4(lo[0], lo[1], lo[2], lo[3]);
    }
}

// ------------------------------ gate ---------------------------------------
__global__ void k_gate(const float* __restrict__ query,
                       const float* __restrict__ w_curv,
                       const float* __restrict__ b_curv)
{
    __shared__ float red[4];
    int b = blockIdx.x, tid = threadIdx.x;
    float s = 0.f;
    for (int h = tid; h < HID; h += 128)
        s += query[(size_t)b * HID + h] * w_curv[h];
#pragma unroll
    for (int o = 16; o; o >>= 1) s += __shfl_xor_sync(0xffffffffu, s, o);
    if ((tid & 31) == 0) red[tid >> 5] = s;
    __syncthreads();
    if (tid == 0) {
        float t = red[0] + red[1] + red[2] + red[3] + b_curv[0];
        g_gate[b] = 1.0f / (1.0f + expf(-t));
    }
}

// --------------------------- top-k (two-phase) ------------------------------
__global__ void k_topk(const float* __restrict__ sim,
                       const float* __restrict__ temperature)
{
    __shared__ float cv[256];
    __shared__ int   ci[256];
    int b = blockIdx.x, tid = threadIdx.x;
    int w = tid >> 5, lane = tid & 31;
    float scale = (0.5f + g_gate[b]) / fmaxf(temperature[0], 1e-6f);

    // phase 1: per-warp top-32 over its 512 elements (registers)
    float v[16];
    const float* row = sim + (size_t)b * MS + w * 512;
#pragma unroll
    for (int j = 0; j < 16; j++) v[j] = row[j * 32 + lane] * scale;

    for (int it = 0; it < NK; it++) {
        float bv = -FLT_MAX; int bj = 0;
#pragma unroll
        for (int j = 0; j < 16; j++)
            if (v[j] > bv) { bv = v[j]; bj = j; }
        int bi = w * 512 + bj * 32 + lane;
#pragma unroll
        for (int o = 16; o; o >>= 1) {
            float ov = __shfl_xor_sync(0xffffffffu, bv, o);
            int   oi = __shfl_xor_sync(0xffffffffu, bi, o);
            if (ov > bv || (ov == bv && oi < bi)) { bv = ov; bi = oi; }
        }
        if ((bi & 31) == lane) v[(bi >> 5) & 15] = -FLT_MAX;
        if (lane == 0) { cv[w * 32 + it] = bv; ci[w * 32 + it] = bi; }
    }
    __syncthreads();

    // phase 2: warp 0 merges 256 candidates
    if (w == 0) {
        float pv[8]; int pi[8];
#pragma unroll
        for (int j = 0; j < 8; j++) { pv[j] = cv[lane + j * 32]; pi[j] = ci[lane + j * 32]; }
        for (int k = 0; k < NK; k++) {
            float bv = -FLT_MAX; int bi = 0x7FFFFFFF;
#pragma unroll
            for (int j = 0; j < 8; j++)
                if (pv[j] > bv || (pv[j] == bv && pi[j] < bi)) { bv = pv[j]; bi = pi[j]; }
#pragma unroll
            for (int o = 16; o; o >>= 1) {
                float ov = __shfl_xor_sync(0xffffffffu, bv, o);
                int   oi = __shfl_xor_sync(0xffffffffu, bi, o);
                if (ov > bv || (ov == bv && oi < bi)) { bv = ov; bi = oi; }
            }
#pragma unroll
            for (int j = 0; j < 8; j++)
                if (pi[j] == bi) pv[j] = -FLT_MAX;
            if (lane == 0) {
                g_vals[(size_t)b * NK + k] = bv;
                g_idx [(size_t)b * NK + k] = bi;
            }
        }
    }
}

// ------------- softmax over M=4096 -> tiled bf16 (hi only) ------------------
__global__ void k_softmax_dec(const float* __restrict__ in, bf16* __restrict__ out)
{
    __shared__ float sv[MS];
    __shared__ float red[256];
    int b = blockIdx.x, tid = threadIdx.x;
    const float* row = in + (size_t)b * MS;
    float mx = -FLT_MAX;
    for (int i = tid; i < MS; i += 256) { float v = row[i]; sv[i] = v; mx = fmaxf(mx, v); }
    red[tid] = mx; __syncthreads();
    for (int off = 128; off; off >>= 1) { if (tid < off) red[tid] = fmaxf(red[tid], red[tid + off]); __syncthreads(); }
    mx = red[0]; __syncthreads();
    float s = 0.f;
    for (int i = tid; i < MS; i += 256) { float e = expf(sv[i] - mx); sv[i] = e; s += e; }
    red[tid] = s; __syncthreads();
    for (int off = 128; off; off >>= 1) { if (tid < off) red[tid] += red[tid + off]; __syncthreads(); }
    float inv = 1.0f / red[0];
    int rb = b >> 7;
    uint32_t rlin = (uint32_t)(b & 127) << 7;
    for (int gI = tid; gI < MS / 8; gI += 256) {
        int c = gI * 8;
        uint32_t hi[4];
#pragma unroll
        for (int j = 0; j < 4; j++)
            hi[j] = pk2(sv[c + 2 * j] * inv, sv[c + 2 * j + 1] * inv);
        uint32_t lin = swz(rlin + ((uint32_t)(c & 63) << 1));
        *(uint4*)((char*)out + ((size_t)rb * (MS / 64) + (c >> 6)) * TILE_B + lin)
            = make_uint4(hi[0], hi[1], hi[2], hi[3]);
    }
}

// ------- combine: softmax(vals + act[idx]); read3 (tiled hi|lo) -------------
__global__ void k_combine(const float* __restrict__ act,
                          const float* __restrict__ mem)
{
    __shared__ float comb[NK];
    __shared__ int   sidx[NK];
    int b = blockIdx.x, tid = threadIdx.x;
    if (tid < NK) {
        int id = g_idx[(size_t)b * NK + tid];
        sidx[tid] = id;
        float t = g_vals[(size_t)b * NK + tid] + act[(size_t)b * MS + id];
        float m = t;
#pragma unroll
        for (int o = 16; o; o >>= 1) m = fmaxf(m, __shfl_xor_sync(0xffffffffu, m, o));
        float e = expf(t - m);
        float s = e;
#pragma unroll
        for (int o = 16; o; o >>= 1) s += __shfl_xor_sync(0xffffffffu, s, o);
        comb[tid] = e / s;
    }
    __syncthreads();
    int rb = b >> 7;
    uint32_t rlin = (uint32_t)(b & 127) << 7;
    if (tid < HID / 8) {
        int h0 = tid * 8;
        float a[8] = {0, 0, 0, 0, 0, 0, 0, 0};
#pragma unroll
        for (int k = 0; k < NK; k++) {
            float cb = comb[k];
            const float4* mr = (const float4*)(mem + (size_t)sidx[k] * HID + h0);
            float4 m0 = mr[0], m1 = mr[1];
            a[0] += cb * m0.x; a[1] += cb * m0.y; a[2] += cb * m0.z; a[3] += cb * m0.w;
            a[4] += cb * m1.x; a[5] += cb * m1.y; a[6] += cb * m1.z; a[7] += cb * m1.w;
        }
        uint32_t hi[4], lo[4];
#pragma unroll
        for (int j = 0; j < 4; j++) {
            bf16 h0b = __float2bfloat16(a[2 * j]), h1b = __float2bfloat16(a[2 * j + 1]);
            __nv_bfloat162 hp; hp.x = h0b; hp.y = h1b;
            hi[j] = *(uint32_t*)&hp;
            lo[j] = pk2(a[2 * j] - __bfloat162float(h0b), a[2 * j + 1] - __bfloat162float(h1b));
        }
        int kb = h0 >> 6;
        uint32_t lin = swz(rlin + ((uint32_t)(h0 & 63) << 1));
        *(uint4*)((char*)g_read3 + ((size_t)rb * (2 * HID / 64) + kb) * TILE_B + lin)
            = make_uint4(hi[0], hi[1], hi[2], hi[3]);
        *(uint4*)((char*)g_read3 + ((size_t)rb * (2 * HID / 64) + kb + HID / 64) * TILE_B + lin)
            = make_uint4(lo[0], lo[1], lo[2], lo[3]);
    }
}

// --------------- broadcast: out[b,s,:] = tanh(orow + b_dec) ----------------
__global__ void k_broadcast(const float* __restrict__ orow,
                            const float* __restrict__ bdec,
                            float* __restrict__ out)
{
    int t = blockIdx.x * blockDim.x + threadIdx.x;
    if (t < BATCH * DIM / 4) {
        int b = t / (DIM / 4), dq = t % (DIM / 4);
        float4 v = ((const float4*)orow)[(size_t)b * (DIM / 4) + dq];
        float4 bb = ((const float4*)bdec)[dq];
        v.x = tanhf(v.x + bb.x); v.y = tanhf(v.y + bb.y);
        v.z = tanhf(v.z + bb.z); v.w = tanhf(v.w + bb.w);
        float4* o = (float4*)out;
#pragma unroll
        for (int s = 0; s < SEQ; s++)
            o[((size_t)b * SEQ + s) * (DIM / 4) + dq] = v;
    }
}

// ---------------------------------------------------------------------------
extern "C" void kernel_launch(void* const* d_in, const int* in_sizes, int n_in,
                              void* d_out, int out_size)
{
    int i = 1;
    if (in_sizes[1] < 16) i = 2;   // skip scalar 'topk' input if present

    const float* x      = (const float*)d_in[0];
    const float* W_enc  = (const float*)d_in[i++];
    const float* b_enc  = (const float*)d_in[i++];
    const float* w_curv = (const float*)d_in[i++];
    const float* b_curv = (const float*)d_in[i++];
    const float* mem    = (const float*)d_in[i++];
    const float* assoc  = (const float*)d_in[i++];
    const float* W_dec  = (const float*)d_in[i++];
    const float* b_dec  = (const float*)d_in[i++];
    const float* temp   = (const float*)d_in[i++];
    float* out = (float*)d_out;

    bf16 *x3, *We3, *mem3, *as1, *Wd3, *q3, *act1, *read3;
    float *query, *sim, *actB, *orow;
    cudaGetSymbolAddress((void**)&x3,    g_x3);
    cudaGetSymbolAddress((void**)&We3,   g_We3);
    cudaGetSymbolAddress((void**)&mem3,  g_mem3);
    cudaGetSymbolAddress((void**)&as1,   g_as);
    cudaGetSymbolAddress((void**)&Wd3,   g_Wd3);
    cudaGetSymbolAddress((void**)&q3,    g_q3);
    cudaGetSymbolAddress((void**)&act1,  g_act);
    cudaGetSymbolAddress((void**)&read3, g_read3);
    cudaGetSymbolAddress((void**)&query, g_query);
    cudaGetSymbolAddress((void**)&sim,   g_sim);
    cudaGetSymbolAddress((void**)&actB,  g_actB);
    cudaGetSymbolAddress((void**)&orow,  g_orow);

    cudaFuncSetAttribute(k_gemm<0>, cudaFuncAttributeMaxDynamicSharedMemorySize, SMEM_BYTES);
    cudaFuncSetAttribute(k_gemm<1>, cudaFuncAttributeMaxDynamicSharedMemorySize, SMEM_BYTES);

    // ---- prep: tiled-swizzled bf16 operands ----
    k_dec_t<<<(int)(((long)BATCH * SEQ * DIM / 8 + 255) / 256), 256>>>(
        x, x3, DIM, (long)BATCH * SEQ * DIM / 8);
    k_dec_t<<<(int)(((long)MS * HID / 8 + 255) / 256), 256>>>(
        mem, mem3, HID, (long)MS * HID / 8);
    k_tdec_t<true><<<dim3(HID / 32, DIM / 32), 256>>>(W_enc, We3, DIM, HID);
    k_tdec_t<false><<<dim3(MS / 32, MS / 32), 256>>>(assoc, as1, MS, MS);
    k_tdec_t<true><<<dim3(DIM / 32, HID / 32), 256>>>(W_dec, Wd3, HID, DIM);

    // ---- encoder GEMM (bf16x3) + fused tanh/bias/mean -> query + q3 ----
    k_gemm<1><<<dim3(HID / 128, BATCH * SEQ / 256), 512, SMEM_BYTES>>>(
        x3, We3, 2 * DIM / 64, 2 * DIM / 64, DIM, 3, nullptr, 0, b_enc, query, q3);
    // ---- gate ----
    k_gate<<<BATCH, 128>>>(query, w_curv, b_curv);
    // ---- sim = query @ mem^T (bf16x3) ----
    k_gemm<0><<<dim3(MS / 128, BATCH / 256), 512, SMEM_BYTES>>>(
        q3, mem3, 2 * HID / 64, 2 * HID / 64, HID, 3, sim, MS, nullptr, nullptr, nullptr);
    // ---- top-k on scaled sim ----
    k_topk<<<BATCH, 256>>>(sim, temp);
    // ---- two rounds of softmax -> @ assoc (plain bf16) ----
    k_softmax_dec<<<BATCH, 256>>>(sim, act1);
    k_gemm<0><<<dim3(MS / 128, BATCH / 256), 512, SMEM_BYTES>>>(
        act1, as1, MS / 64, MS / 64, MS, 1, actB, MS, nullptr, nullptr, nullptr);
    k_softmax_dec<<<BATCH, 256>>>(actB, act1);
    k_gemm<0><<<dim3(MS / 128, BATCH / 256), 512, SMEM_BYTES>>>(
        act1, as1, MS / 64, MS / 64, MS, 1, actB, MS, nullptr, nullptr, nullptr);
    // ---- combine + gather-read (-> tiled bf16 hi|lo) ----
    k_combine<<<BATCH, 256>>>(actB, mem);
    // ---- decoder GEMM (bf16x3) ----
    k_gemm<0><<<dim3(DIM / 128, BATCH / 256), 512, SMEM_BYTES>>>(
        read3, Wd3, 2 * HID / 64, 2 * HID / 64, HID, 3, orow, DIM, nullptr, nullptr, nullptr);
    // ---- bias + tanh + broadcast over S ----
    k_broadcast<<<(BATCH * DIM / 4 + 255) / 256, 256>>>(orow, b_dec, out);
}

// round 5
// speedup vs baseline: 5.0693x; 1.0668x over previous
#include <cuda_runtime.h>
#include <cuda_bf16.h>
#include <math.h>
#include <float.h>
#include <stdint.h>

#define BATCH 2048
#define SEQ   32
#define DIM   1024
#define HID   1024
#define MS    4096
#define NK    32

typedef __nv_bfloat16 bf16;

// Tiled layout: tile = 128 rows x 64 cols bf16 = 16KB, SW128-swizzled.
#define TILE_E 8192
#define TILE_B 16384

// ------------------------------- scratch -----------------------------------
__device__ bf16 g_x3[(size_t)BATCH * SEQ * 2 * DIM];
__device__ bf16 g_We3[(size_t)HID * 2 * DIM];
__device__ bf16 g_mem3[(size_t)MS * 2 * HID];
__device__ bf16 g_as[(size_t)MS * MS];
__device__ bf16 g_Wd3[(size_t)DIM * 2 * HID];
__device__ bf16 g_q3[(size_t)BATCH * 2 * HID];
__device__ bf16 g_act[(size_t)BATCH * MS];
__device__ bf16 g_read3[(size_t)BATCH * 2 * HID];
__device__ float g_query[(size_t)BATCH * HID];
__device__ float g_sim[(size_t)BATCH * MS];
__device__ float g_actB[(size_t)BATCH * MS];
__device__ float g_orow[(size_t)BATCH * DIM];
__device__ float g_gate[BATCH];
__device__ float g_vals[BATCH * NK];
__device__ int   g_idx[BATCH * NK];

// ------------------------------ helpers ------------------------------------
__device__ __forceinline__ uint32_t s2u(const void* p) {
    uint32_t a;
    asm("{ .reg .u64 t; cvta.to.shared.u64 t, %1; cvt.u32.u64 %0, t; }" : "=r"(a) : "l"(p));
    return a;
}
__device__ __forceinline__ uint32_t swz(uint32_t lin) {
    return lin ^ ((lin >> 3) & 0x70u);
}
__device__ __forceinline__ void ldsm4(uint32_t* r, uint32_t a) {
    asm volatile("ldmatrix.sync.aligned.m8n8.x4.shared.b16 {%0,%1,%2,%3}, [%4];"
        : "=r"(r[0]), "=r"(r[1]), "=r"(r[2]), "=r"(r[3]) : "r"(a));
}
__device__ __forceinline__ void ldsm2(uint32_t* r, uint32_t a) {
    asm volatile("ldmatrix.sync.aligned.m8n8.x2.shared.b16 {%0,%1}, [%2];"
        : "=r"(r[0]), "=r"(r[1]) : "r"(a));
}
__device__ __forceinline__ void mma16816(float* c, const uint32_t* a, const uint32_t* b) {
    asm volatile("mma.sync.aligned.m16n8k16.row.col.f32.bf16.bf16.f32 "
        "{%0,%1,%2,%3}, {%4,%5,%6,%7}, {%8,%9}, {%0,%1,%2,%3};"
        : "+f"(c[0]), "+f"(c[1]), "+f"(c[2]), "+f"(c[3])
        : "r"(a[0]), "r"(a[1]), "r"(a[2]), "r"(a[3]), "r"(b[0]), "r"(b[1]));
}
__device__ __forceinline__ float fast_tanh(float x) {
    float ax = fabsf(x);
    float t = __expf(-2.0f * ax);
    float r = (1.0f - t) / (1.0f + t);
    return copysignf(r, x);
}
__device__ __forceinline__ uint32_t pk2(float a, float b) {
    __nv_bfloat162 h;
    h.x = __float2bfloat16(a); h.y = __float2bfloat16(b);
    return *(uint32_t*)&h;
}

#define MBARRIER_INIT(mb, c) \
    asm volatile("mbarrier.init.shared.b64 [%0], %1;" :: "r"((uint32_t)(mb)), "r"((uint32_t)(c)) : "memory")
#define MBAR_ARRIVE_EXPECT(mb, tx) \
    asm volatile("mbarrier.arrive.expect_tx.shared.b64 _, [%0], %1;" :: "r"((uint32_t)(mb)), "r"((uint32_t)(tx)) : "memory")
#define BULK_G2S(dst, src, bytes, mb) \
    asm volatile("cp.async.bulk.shared::cluster.global.mbarrier::complete_tx::bytes [%0], [%1], %2, [%3];" \
        :: "r"((uint32_t)(dst)), "l"(src), "r"((uint32_t)(bytes)), "r"((uint32_t)(mb)) : "memory")
#define MBARRIER_WAIT_PARITY(mb, ph) do {                                              \
    uint32_t _mb = (uint32_t)(mb); uint32_t _ph = (uint32_t)(ph); uint32_t _done;      \
    asm volatile("{\n .reg .pred p;\n"                                                 \
        " mbarrier.try_wait.parity.acquire.cta.shared::cta.b64 p, [%1], %2;\n"         \
        " selp.b32 %0, 1, 0, p;\n}"                                                    \
        : "=r"(_done) : "r"(_mb), "r"(_ph) : "memory");                                \
    if (!_done) {                                                                      \
        asm volatile("{\n .reg .pred P1;\n"                                            \
            "WL_%=:\n"                                                                 \
            " mbarrier.try_wait.parity.acquire.cta.shared::cta.b64 P1, [%0], %1, 0x989680;\n" \
            " @P1 bra.uni WD_%=;\n bra.uni WL_%=;\nWD_%=:\n}"                          \
            :: "r"(_mb), "r"(_ph) : "memory");                                         \
    }                                                                                  \
} while (0)

// ----------------------------- GEMM ----------------------------------------
// C[M,N] = A @ B^T, tiled-swizzled bf16 operands.
// BM=256, BN=128, BK=64. 512 threads, 16 warps 4x4, warp tile 64x32.
// TERMS==3: fat chunks — per k-chunk load {A hi,lo}x2 + {B hi,lo} (96KB),
//   run 3 register passes: Ahi*Bhi, Ahi*Blo, Alo*Bhi.  2 stages.
// TERMS==1: plain bf16, 48KB chunks, 4 stages.
#define SMEM_BYTES (1024 + 196608)

template <int EPI, int TERMS>
__global__ void __launch_bounds__(512, 1)
k_gemm(const bf16* __restrict__ A, const bf16* __restrict__ B,
       int nkbA, int nkbB, int K,
       float* __restrict__ C, int Nst,
       const float* __restrict__ bias,
       float* __restrict__ qout, bf16* __restrict__ q3out)
{
    extern __shared__ char smem[];
    const uint32_t sb = s2u(smem);
    const int tid = threadIdx.x, wid = tid >> 5, lane = tid & 31;
    const int wr = wid >> 2, wc = wid & 3;
    const int m0 = blockIdx.y * 256, n0 = blockIdx.x * 128;
    const int Kb = K / 64;
    const int rbA0 = blockIdx.y * 2;
    const int nb = blockIdx.x;

    if (tid == 0) {
#pragma unroll
        for (int s = 0; s < 4; s++) MBARRIER_INIT(sb + s * 8, 1);
    }
    __syncthreads();

    const uint32_t aTileSel = (wr >= 2) ? (uint32_t)TILE_B : 0u;
    uint32_t alin[4], blin[4];
#pragma unroll
    for (int mi = 0; mi < 4; mi++)
        alin[mi] = (uint32_t)(((wr & 1) * 64) + mi * 16 + (lane & 15)) * 128u + (uint32_t)(lane >> 4) * 16u;
#pragma unroll
    for (int ni = 0; ni < 4; ni++)
        blin[ni] = (uint32_t)(wc * 32 + ni * 8 + (lane & 7)) * 128u + (uint32_t)((lane >> 3) & 1) * 16u;

    float acc[4][4][4];
#pragma unroll
    for (int a = 0; a < 4; a++)
#pragma unroll
        for (int b = 0; b < 4; b++)
#pragma unroll
            for (int c = 0; c < 4; c++) acc[a][b][c] = 0.f;

    if (TERMS == 3) {
        // ---------------- fat-chunk path: 2 stages x 96KB -------------------
        const int NC = Kb;
        if (tid == 0) {
#pragma unroll
            for (int c0 = 0; c0 < 2; c0++) {
                if (c0 >= NC) break;
                uint32_t mb = sb + (uint32_t)c0 * 8;
                uint32_t dst = sb + 1024u + (uint32_t)c0 * 98304u;
                MBAR_ARRIVE_EXPECT(mb, 98304u);
                BULK_G2S(dst,           A + ((size_t)rbA0 * nkbA + c0) * TILE_E, TILE_B, mb);
                BULK_G2S(dst + 16384u,  A + ((size_t)(rbA0 + 1) * nkbA + c0) * TILE_E, TILE_B, mb);
                BULK_G2S(dst + 32768u,  A + ((size_t)rbA0 * nkbA + c0 + Kb) * TILE_E, TILE_B, mb);
                BULK_G2S(dst + 49152u,  A + ((size_t)(rbA0 + 1) * nkbA + c0 + Kb) * TILE_E, TILE_B, mb);
                BULK_G2S(dst + 65536u,  B + ((size_t)nb * nkbB + c0) * TILE_E, TILE_B, mb);
                BULK_G2S(dst + 81920u,  B + ((size_t)nb * nkbB + c0 + Kb) * TILE_E, TILE_B, mb);
            }
        }
        for (int c = 0; c < NC; c++) {
            int s = c & 1;
            MBARRIER_WAIT_PARITY(sb + s * 8, (c >> 1) & 1);
            const uint32_t stg = sb + 1024u + (uint32_t)s * 98304u;
            const uint32_t Ah = stg + aTileSel;
            const uint32_t Al = stg + 32768u + aTileSel;
            const uint32_t Bh = stg + 65536u;
            const uint32_t Bl = stg + 81920u;
#pragma unroll
            for (int ks = 0; ks < 4; ks++) {
                uint32_t af[4][4], bh[4][2], bl[4][2];
#pragma unroll
                for (int mi = 0; mi < 4; mi++) ldsm4(af[mi], Ah + swz(alin[mi] + ks * 32u));
#pragma unroll
                for (int ni = 0; ni < 4; ni++) ldsm2(bh[ni], Bh + swz(blin[ni] + ks * 32u));
#pragma unroll
                for (int ni = 0; ni < 4; ni++) ldsm2(bl[ni], Bl + swz(blin[ni] + ks * 32u));
#pragma unroll
                for (int mi = 0; mi < 4; mi++)
#pragma unroll
                    for (int ni = 0; ni < 4; ni++) mma16816(acc[mi][ni], af[mi], bh[ni]);
#pragma unroll
                for (int mi = 0; mi < 4; mi++)
#pragma unroll
                    for (int ni = 0; ni < 4; ni++) mma16816(acc[mi][ni], af[mi], bl[ni]);
#pragma unroll
                for (int mi = 0; mi < 4; mi++) ldsm4(af[mi], Al + swz(alin[mi] + ks * 32u));
#pragma unroll
                for (int mi = 0; mi < 4; mi++)
#pragma unroll
                    for (int ni = 0; ni < 4; ni++) mma16816(acc[mi][ni], af[mi], bh[ni]);
            }
            __syncthreads();
            if (c + 2 < NC && tid == 0) {
                int cn = c + 2;
                uint32_t mb = sb + (uint32_t)s * 8;
                uint32_t dst = sb + 1024u + (uint32_t)s * 98304u;
                MBAR_ARRIVE_EXPECT(mb, 98304u);
                BULK_G2S(dst,           A + ((size_t)rbA0 * nkbA + cn) * TILE_E, TILE_B, mb);
                BULK_G2S(dst + 16384u,  A + ((size_t)(rbA0 + 1) * nkbA + cn) * TILE_E, TILE_B, mb);
                BULK_G2S(dst + 32768u,  A + ((size_t)rbA0 * nkbA + cn + Kb) * TILE_E, TILE_B, mb);
                BULK_G2S(dst + 49152u,  A + ((size_t)(rbA0 + 1) * nkbA + cn + Kb) * TILE_E, TILE_B, mb);
                BULK_G2S(dst + 65536u,  B + ((size_t)nb * nkbB + cn) * TILE_E, TILE_B, mb);
                BULK_G2S(dst + 81920u,  B + ((size_t)nb * nkbB + cn + Kb) * TILE_E, TILE_B, mb);
            }
        }
    } else {
        // ---------------- plain path: 4 stages x 48KB -----------------------
        const int NC = Kb;
        if (tid == 0) {
#pragma unroll
            for (int c0 = 0; c0 < 3; c0++) {
                if (c0 >= NC) break;
                uint32_t mb = sb + (uint32_t)c0 * 8;
                uint32_t dst = sb + 1024u + (uint32_t)c0 * 49152u;
                MBAR_ARRIVE_EXPECT(mb, 49152u);
                BULK_G2S(dst,              A + ((size_t)rbA0 * nkbA + c0) * TILE_E, TILE_B, mb);
                BULK_G2S(dst + TILE_B,     A + ((size_t)(rbA0 + 1) * nkbA + c0) * TILE_E, TILE_B, mb);
                BULK_G2S(dst + 2 * TILE_B, B + ((size_t)nb * nkbB + c0) * TILE_E, TILE_B, mb);
            }
        }
        for (int c = 0; c < NC; c++) {
            int s = c & 3;
            MBARRIER_WAIT_PARITY(sb + s * 8, (c >> 2) & 1);
            const uint32_t As = sb + 1024u + (uint32_t)s * 49152u + aTileSel;
            const uint32_t Bs = sb + 1024u + (uint32_t)s * 49152u + 2u * TILE_B;
#pragma unroll
            for (int ks = 0; ks < 4; ks++) {
                uint32_t af[4][4], bfr[4][2];
#pragma unroll
                for (int mi = 0; mi < 4; mi++) ldsm4(af[mi], As + swz(alin[mi] + ks * 32u));
#pragma unroll
                for (int ni = 0; ni < 4; ni++) ldsm2(bfr[ni], Bs + swz(blin[ni] + ks * 32u));
#pragma unroll
                for (int mi = 0; mi < 4; mi++)
#pragma unroll
                    for (int ni = 0; ni < 4; ni++) mma16816(acc[mi][ni], af[mi], bfr[ni]);
            }
            __syncthreads();
            if (c + 3 < NC && tid == 0) {
                int cn = c + 3;
                int sn = cn & 3;
                uint32_t mb = sb + (uint32_t)sn * 8;
                uint32_t dst = sb + 1024u + (uint32_t)sn * 49152u;
                MBAR_ARRIVE_EXPECT(mb, 49152u);
                BULK_G2S(dst,              A + ((size_t)rbA0 * nkbA + cn) * TILE_E, TILE_B, mb);
                BULK_G2S(dst + TILE_B,     A + ((size_t)(rbA0 + 1) * nkbA + cn) * TILE_E, TILE_B, mb);
                BULK_G2S(dst + 2 * TILE_B, B + ((size_t)nb * nkbB + cn) * TILE_E, TILE_B, mb);
            }
        }
    }

    if (EPI == 0) {
#pragma unroll
        for (int mi = 0; mi < 4; mi++) {
            int r = m0 + wr * 64 + mi * 16 + (lane >> 2);
#pragma unroll
            for (int ni = 0; ni < 4; ni++) {
                int col = n0 + wc * 32 + ni * 8 + 2 * (lane & 3);
                *(float2*)&C[(size_t)r * Nst + col] = make_float2(acc[mi][ni][0], acc[mi][ni][1]);
                *(float2*)&C[(size_t)(r + 8) * Nst + col] = make_float2(acc[mi][ni][2], acc[mi][ni][3]);
            }
        }
    } else {
        // rows = batch*SEQ; 32-row group = one batch; warp holds 2 batches.
#pragma unroll
        for (int b = 0; b < 2; b++) {
            int batch = m0 / 32 + wr * 2 + b;
#pragma unroll
            for (int ni = 0; ni < 4; ni++) {
                int col0 = n0 + wc * 32 + ni * 8 + 2 * (lane & 3);
                float bi0 = bias[col0], bi1 = bias[col0 + 1];
                float s0 = 0.f, s1 = 0.f;
#pragma unroll
                for (int mh = 0; mh < 2; mh++) {
                    float* cc = acc[b * 2 + mh][ni];
                    s0 += fast_tanh(cc[0] + bi0) + fast_tanh(cc[2] + bi0);
                    s1 += fast_tanh(cc[1] + bi1) + fast_tanh(cc[3] + bi1);
                }
#pragma unroll
                for (int o = 4; o <= 16; o <<= 1) {
                    s0 += __shfl_xor_sync(0xffffffffu, s0, o);
                    s1 += __shfl_xor_sync(0xffffffffu, s1, o);
                }
                if (lane < 4) {
                    float q0 = s0 * (1.0f / SEQ), q1 = s1 * (1.0f / SEQ);
                    qout[(size_t)batch * HID + col0] = q0;
                    qout[(size_t)batch * HID + col0 + 1] = q1;
                    uint32_t lin = swz(((uint32_t)(batch & 127) << 7) + ((uint32_t)(col0 & 63) << 1));
                    int rb = batch >> 7, kb = col0 >> 6;
                    char* th = (char*)q3out + ((size_t)rb * (2 * HID / 64) + kb) * TILE_B + lin;
                    char* tl = (char*)q3out + ((size_t)rb * (2 * HID / 64) + kb + HID / 64) * TILE_B + lin;
                    bf16 h0 = __float2bfloat16(q0), h1 = __float2bfloat16(q1);
                    *(uint32_t*)th = pk2(q0, q1);
                    *(uint32_t*)tl = pk2(q0 - __bfloat162float(h0), q1 - __bfloat162float(h1));
                }
            }
        }
    }
}

// ---------------------- prep: row-major fp32 -> tiled hi|lo ----------------
__global__ void k_dec_t(const float* __restrict__ in, bf16* __restrict__ out,
                        int K, long nGran)
{
    long g = (long)blockIdx.x * 256 + threadIdx.x;
    if (g >= nGran) return;
    int perRow = K / 8;
    long r = g / perRow;
    int c = (int)(g % perRow) * 8;
    float4 v0 = *(const float4*)(in + r * K + c);
    float4 v1 = *(const float4*)(in + r * K + c + 4);
    float f[8] = {v0.x, v0.y, v0.z, v0.w, v1.x, v1.y, v1.z, v1.w};
    uint32_t hi[4], lo[4];
#pragma unroll
    for (int j = 0; j < 4; j++) {
        bf16 h0 = __float2bfloat16(f[2 * j]), h1 = __float2bfloat16(f[2 * j + 1]);
        __nv_bfloat162 hp; hp.x = h0; hp.y = h1;
        hi[j] = *(uint32_t*)&hp;
        lo[j] = pk2(f[2 * j] - __bfloat162float(h0), f[2 * j + 1] - __bfloat162float(h1));
    }
    int rb = (int)(r >> 7), kb = c >> 6, kbT = 2 * K / 64;
    uint32_t lin = swz(((uint32_t)(r & 127) << 7) + ((uint32_t)(c & 63) << 1));
    *(uint4*)((char*)out + ((size_t)rb * kbT + kb) * TILE_B + lin) = make_uint4(hi[0], hi[1], hi[2], hi[3]);
    *(uint4*)((char*)out + ((size_t)rb * kbT + kb + K / 64) * TILE_B + lin) = make_uint4(lo[0], lo[1], lo[2], lo[3]);
}

// ------------- prep: transpose fp32 [K][N] -> tiled rows=n ------------------
template <bool LO>
__global__ void k_tdec_t(const float* __restrict__ in, bf16* __restrict__ out,
                         int K, int N)
{
    __shared__ float tile[32][33];
    int n0 = blockIdx.x * 32, k0 = blockIdx.y * 32;
    int tx = threadIdx.x & 31, ty = threadIdx.x >> 5;
    for (int r = ty; r < 32; r += 8)
        tile[r][tx] = in[(size_t)(k0 + r) * N + n0 + tx];
    __syncthreads();
    int t = threadIdx.x;
    if (t < 128) {
        int nl = t & 31, kg = t >> 5;
        float f[8];
#pragma unroll
        for (int j = 0; j < 8; j++) f[j] = tile[kg * 8 + j][nl];
        int n = n0 + nl, k = k0 + kg * 8;
        uint32_t hi[4], lo[4];
#pragma unroll
        for (int j = 0; j < 4; j++) {
            bf16 h0 = __float2bfloat16(f[2 * j]), h1 = __float2bfloat16(f[2 * j + 1]);
            __nv_bfloat162 hp; hp.x = h0; hp.y = h1;
            hi[j] = *(uint32_t*)&hp;
            if (LO)
                lo[j] = pk2(f[2 * j] - __bfloat162float(h0), f[2 * j + 1] - __bfloat162float(h1));
        }
        int rb = n >> 7, kb = k >> 6;
        int kbT = LO ? 2 * K / 64 : K / 64;
        uint32_t lin = swz(((uint32_t)(n & 127) << 7) + ((uint32_t)(k & 63) << 1));
        *(uint4*)((char*)out + ((size_t)rb * kbT + kb) * TILE_B + lin) = make_uint4(hi[0], hi[1], hi[2], hi[3]);
        if (LO)
            *(uint4*)((char*)out + ((size_t)rb * kbT + kb + K / 64) * TILE_B + lin) = make_uint4(lo[0], lo[1], lo[2], lo[3]);
    }
}

// ------------------------------ gate ---------------------------------------
__global__ void k_gate(const float* __restrict__ query,
                       const float* __restrict__ w_curv,
                       const float* __restrict__ b_curv)
{
    __shared__ float red[4];
    int b = blockIdx.x, tid = threadIdx.x;
    float s = 0.f;
    for (int h = tid; h < HID; h += 128)
        s += query[(size_t)b * HID + h] * w_curv[h];
#pragma unroll
    for (int o = 16; o; o >>= 1) s += __shfl_xor_sync(0xffffffffu, s, o);
    if ((tid & 31) == 0) red[tid >> 5] = s;
    __syncthreads();
    if (tid == 0) {
        float t = red[0] + red[1] + red[2] + red[3] + b_curv[0];
        g_gate[b] = 1.0f / (1.0f + expf(-t));
    }
}

// --------------------------- top-k (two-phase) ------------------------------
__global__ void k_topk(const float* __restrict__ sim,
                       const float* __restrict__ temperature)
{
    __shared__ float cv[256];
    __shared__ int   ci[256];
    int b = blockIdx.x, tid = threadIdx.x;
    int w = tid >> 5, lane = tid & 31;
    float scale = (0.5f + g_gate[b]) / fmaxf(temperature[0], 1e-6f);

    float v[16];
    const float* row = sim + (size_t)b * MS + w * 512;
#pragma unroll
    for (int j = 0; j < 16; j++) v[j] = row[j * 32 + lane] * scale;

    for (int it = 0; it < NK; it++) {
        float bv = -FLT_MAX; int bj = 0;
#pragma unroll
        for (int j = 0; j < 16; j++)
            if (v[j] > bv) { bv = v[j]; bj = j; }
        int bi = w * 512 + bj * 32 + lane;
#pragma unroll
        for (int o = 16; o; o >>= 1) {
            float ov = __shfl_xor_sync(0xffffffffu, bv, o);
            int   oi = __shfl_xor_sync(0xffffffffu, bi, o);
            if (ov > bv || (ov == bv && oi < bi)) { bv = ov; bi = oi; }
        }
        if ((bi & 31) == lane) v[(bi >> 5) & 15] = -FLT_MAX;
        if (lane == 0) { cv[w * 32 + it] = bv; ci[w * 32 + it] = bi; }
    }
    __syncthreads();

    if (w == 0) {
        float pv[8]; int pi[8];
#pragma unroll
        for (int j = 0; j < 8; j++) { pv[j] = cv[lane + j * 32]; pi[j] = ci[lane + j * 32]; }
        for (int k = 0; k < NK; k++) {
            float bv = -FLT_MAX; int bi = 0x7FFFFFFF;
#pragma unroll
            for (int j = 0; j < 8; j++)
                if (pv[j] > bv || (pv[j] == bv && pi[j] < bi)) { bv = pv[j]; bi = pi[j]; }
#pragma unroll
            for (int o = 16; o; o >>= 1) {
                float ov = __shfl_xor_sync(0xffffffffu, bv, o);
                int   oi = __shfl_xor_sync(0xffffffffu, bi, o);
                if (ov > bv || (ov == bv && oi < bi)) { bv = ov; bi = oi; }
            }
#pragma unroll
            for (int j = 0; j < 8; j++)
                if (pi[j] == bi) pv[j] = -FLT_MAX;
            if (lane == 0) {
                g_vals[(size_t)b * NK + k] = bv;
                g_idx [(size_t)b * NK + k] = bi;
            }
        }
    }
}

// ------------- softmax over M=4096 -> tiled bf16 (hi only) ------------------
__global__ void k_softmax_dec(const float* __restrict__ in, bf16* __restrict__ out)
{
    __shared__ float sv[MS];
    __shared__ float red[256];
    int b = blockIdx.x, tid = threadIdx.x;
    const float* row = in + (size_t)b * MS;
    float mx = -FLT_MAX;
    for (int i = tid; i < MS; i += 256) { float v = row[i]; sv[i] = v; mx = fmaxf(mx, v); }
    red[tid] = mx; __syncthreads();
    for (int off = 128; off; off >>= 1) { if (tid < off) red[tid] = fmaxf(red[tid], red[tid + off]); __syncthreads(); }
    mx = red[0]; __syncthreads();
    float s = 0.f;
    for (int i = tid; i < MS; i += 256) { float e = expf(sv[i] - mx); sv[i] = e; s += e; }
    red[tid] = s; __syncthreads();
    for (int off = 128; off; off >>= 1) { if (tid < off) red[tid] += red[tid + off]; __syncthreads(); }
    float inv = 1.0f / red[0];
    int rb = b >> 7;
    uint32_t rlin = (uint32_t)(b & 127) << 7;
    for (int gI = tid; gI < MS / 8; gI += 256) {
        int c = gI * 8;
        uint32_t hi[4];
#pragma unroll
        for (int j = 0; j < 4; j++)
            hi[j] = pk2(sv[c + 2 * j] * inv, sv[c + 2 * j + 1] * inv);
        uint32_t lin = swz(rlin + ((uint32_t)(c & 63) << 1));
        *(uint4*)((char*)out + ((size_t)rb * (MS / 64) + (c >> 6)) * TILE_B + lin)
            = make_uint4(hi[0], hi[1], hi[2], hi[3]);
    }
}

// ------- combine: softmax(vals + act[idx]); read3 (tiled hi|lo) -------------
__global__ void k_combine(const float* __restrict__ act,
                          const float* __restrict__ mem)
{
    __shared__ float comb[NK];
    __shared__ int   sidx[NK];
    int b = blockIdx.x, tid = threadIdx.x;
    if (tid < NK) {
        int id = g_idx[(size_t)b * NK + tid];
        sidx[tid] = id;
        float t = g_vals[(size_t)b * NK + tid] + act[(size_t)b * MS + id];
        float m = t;
#pragma unroll
        for (int o = 16; o; o >>= 1) m = fmaxf(m, __shfl_xor_sync(0xffffffffu, m, o));
        float e = expf(t - m);
        float s = e;
#pragma unroll
        for (int o = 16; o; o >>= 1) s += __shfl_xor_sync(0xffffffffu, s, o);
        comb[tid] = e / s;
    }
    __syncthreads();
    int rb = b >> 7;
    uint32_t rlin = (uint32_t)(b & 127) << 7;
    if (tid < HID / 8) {
        int h0 = tid * 8;
        float a[8] = {0, 0, 0, 0, 0, 0, 0, 0};
#pragma unroll
        for (int k = 0; k < NK; k++) {
            float cb = comb[k];
            const float4* mr = (const float4*)(mem + (size_t)sidx[k] * HID + h0);
            float4 m0 = mr[0], m1 = mr[1];
            a[0] += cb * m0.x; a[1] += cb * m0.y; a[2] += cb * m0.z; a[3] += cb * m0.w;
            a[4] += cb * m1.x; a[5] += cb * m1.y; a[6] += cb * m1.z; a[7] += cb * m1.w;
        }
        uint32_t hi[4], lo[4];
#pragma unroll
        for (int j = 0; j < 4; j++) {
            bf16 h0b = __float2bfloat16(a[2 * j]), h1b = __float2bfloat16(a[2 * j + 1]);
            __nv_bfloat162 hp; hp.x = h0b; hp.y = h1b;
            hi[j] = *(uint32_t*)&hp;
            lo[j] = pk2(a[2 * j] - __bfloat162float(h0b), a[2 * j + 1] - __bfloat162float(h1b));
        }
        int kb = h0 >> 6;
        uint32_t lin = swz(rlin + ((uint32_t)(h0 & 63) << 1));
        *(uint4*)((char*)g_read3 + ((size_t)rb * (2 * HID / 64) + kb) * TILE_B + lin)
            = make_uint4(hi[0], hi[1], hi[2], hi[3]);
        *(uint4*)((char*)g_read3 + ((size_t)rb * (2 * HID / 64) + kb + HID / 64) * TILE_B + lin)
            = make_uint4(lo[0], lo[1], lo[2], lo[3]);
    }
}

// --------------- broadcast: out[b,s,:] = tanh(orow + b_dec) ----------------
__global__ void k_broadcast(const float* __restrict__ orow,
                            const float* __restrict__ bdec,
                            float* __restrict__ out)
{
    int t = blockIdx.x * blockDim.x + threadIdx.x;
    if (t < BATCH * DIM / 4) {
        int b = t / (DIM / 4), dq = t % (DIM / 4);
        float4 v = ((const float4*)orow)[(size_t)b * (DIM / 4) + dq];
        float4 bb = ((const float4*)bdec)[dq];
        v.x = tanhf(v.x + bb.x); v.y = tanhf(v.y + bb.y);
        v.z = tanhf(v.z + bb.z); v.w = tanhf(v.w + bb.w);
        float4* o = (float4*)out;
#pragma unroll
        for (int s = 0; s < SEQ; s++)
            o[((size_t)b * SEQ + s) * (DIM / 4) + dq] = v;
    }
}

// ---------------------------------------------------------------------------
extern "C" void kernel_launch(void* const* d_in, const int* in_sizes, int n_in,
                              void* d_out, int out_size)
{
    int i = 1;
    if (in_sizes[1] < 16) i = 2;   // skip scalar 'topk' input if present

    const float* x      = (const float*)d_in[0];
    const float* W_enc  = (const float*)d_in[i++];
    const float* b_enc  = (const float*)d_in[i++];
    const float* w_curv = (const float*)d_in[i++];
    const float* b_curv = (const float*)d_in[i++];
    const float* mem    = (const float*)d_in[i++];
    const float* assoc  = (const float*)d_in[i++];
    const float* W_dec  = (const float*)d_in[i++];
    const float* b_dec  = (const float*)d_in[i++];
    const float* temp   = (const float*)d_in[i++];
    float* out = (float*)d_out;

    bf16 *x3, *We3, *mem3, *as1, *Wd3, *q3, *act1, *read3;
    float *query, *sim, *actB, *orow;
    cudaGetSymbolAddress((void**)&x3,    g_x3);
    cudaGetSymbolAddress((void**)&We3,   g_We3);
    cudaGetSymbolAddress((void**)&mem3,  g_mem3);
    cudaGetSymbolAddress((void**)&as1,   g_as);
    cudaGetSymbolAddress((void**)&Wd3,   g_Wd3);
    cudaGetSymbolAddress((void**)&q3,    g_q3);
    cudaGetSymbolAddress((void**)&act1,  g_act);
    cudaGetSymbolAddress((void**)&read3, g_read3);
    cudaGetSymbolAddress((void**)&query, g_query);
    cudaGetSymbolAddress((void**)&sim,   g_sim);
    cudaGetSymbolAddress((void**)&actB,  g_actB);
    cudaGetSymbolAddress((void**)&orow,  g_orow);

    cudaFuncSetAttribute(k_gemm<0, 3>, cudaFuncAttributeMaxDynamicSharedMemorySize, SMEM_BYTES);
    cudaFuncSetAttribute(k_gemm<1, 3>, cudaFuncAttributeMaxDynamicSharedMemorySize, SMEM_BYTES);
    cudaFuncSetAttribute(k_gemm<0, 1>, cudaFuncAttributeMaxDynamicSharedMemorySize, SMEM_BYTES);

    // ---- prep ----
    k_dec_t<<<(int)(((long)BATCH * SEQ * DIM / 8 + 255) / 256), 256>>>(
        x, x3, DIM, (long)BATCH * SEQ * DIM / 8);
    k_dec_t<<<(int)(((long)MS * HID / 8 + 255) / 256), 256>>>(
        mem, mem3, HID, (long)MS * HID / 8);
    k_tdec_t<true><<<dim3(HID / 32, DIM / 32), 256>>>(W_enc, We3, DIM, HID);
    k_tdec_t<false><<<dim3(MS / 32, MS / 32), 256>>>(assoc, as1, MS, MS);
    k_tdec_t<true><<<dim3(DIM / 32, HID / 32), 256>>>(W_dec, Wd3, HID, DIM);

    // ---- encoder GEMM (bf16x3 fat) + fused tanh/bias/mean ----
    k_gemm<1, 3><<<dim3(HID / 128, BATCH * SEQ / 256), 512, SMEM_BYTES>>>(
        x3, We3, 2 * DIM / 64, 2 * DIM / 64, DIM, nullptr, 0, b_enc, query, q3);
    // ---- gate ----
    k_gate<<<BATCH, 128>>>(query, w_curv, b_curv);
    // ---- sim = query @ mem^T ----
    k_gemm<0, 3><<<dim3(MS / 128, BATCH / 256), 512, SMEM_BYTES>>>(
        q3, mem3, 2 * HID / 64, 2 * HID / 64, HID, sim, MS, nullptr, nullptr, nullptr);
    // ---- top-k ----
    k_topk<<<BATCH, 256>>>(sim, temp);
    // ---- softmax -> assoc (x2, plain bf16) ----
    k_softmax_dec<<<BATCH, 256>>>(sim, act1);
    k_gemm<0, 1><<<dim3(MS / 128, BATCH / 256), 512, SMEM_BYTES>>>(
        act1, as1, MS / 64, MS / 64, MS, actB, MS, nullptr, nullptr, nullptr);
    k_softmax_dec<<<BATCH, 256>>>(actB, act1);
    k_gemm<0, 1><<<dim3(MS / 128, BATCH / 256), 512, SMEM_BYTES>>>(
        act1, as1, MS / 64, MS / 64, MS, actB, MS, nullptr, nullptr, nullptr);
    // ---- combine + gather-read ----
    k_combine<<<BATCH, 256>>>(actB, mem);
    // ---- decoder GEMM ----
    k_gemm<0, 3><<<dim3(DIM / 128, BATCH / 256), 512, SMEM_BYTES>>>(
        read3, Wd3, 2 * HID / 64, 2 * HID / 64, HID, orow, DIM, nullptr, nullptr, nullptr);
    // ---- bias + tanh + broadcast ----
    k_broadcast<<<(BATCH * DIM / 4 + 255) / 256, 256>>>(orow, b_dec, out);
}